// round 10
// baseline (speedup 1.0000x reference)
#include <cuda_runtime.h>
#include <cuda_bf16.h>
#include <cstdint>
#include <cstddef>

// ---------------------------------------------------------------------------
// TreeRNNCell: out = tanh( mask*(x@W_in + b_in) + segsum(h[src]->dst)@W_aggr + b_aggr )
// N = 500000, E = 500000, X = H = 128.
//
// R9: same algebraic split as R8 (agg@W_aggr = scatter_sum(h@W_aggr)) with:
//   - single frag buffer (~95 regs) so __launch_bounds__(256,2) gives a real
//     2 CTAs/SM (16 warps) without spills; cross-warp hiding replaces the
//     register double-buffer.
//   - agg zeroing fused into gemm1's persistent tile loop (zero_kernel gone).
// Pipeline: prep_w -> gemm1(hW=h@W_aggr, zero agg) -> scatter(hW) -> gemm2.
// ---------------------------------------------------------------------------

#define MAXN 500000
#define NPAD 500032  // ntiles*64 rounding for fused agg-zero
__device__ float g_agg[(size_t)NPAD * 128];
__device__ float g_hw[(size_t)MAXN * 128];
// 4 images: [Win_hi, Win_lo, Wag_hi, Wag_lo], each [128n][64 uint] = bf16x2[n][k]
__device__ __align__(16) unsigned int g_wimg[4 * 8192];

__device__ __forceinline__ float tanh_fast(float x) {
    float r; asm("tanh.approx.f32 %0, %1;" : "=f"(r) : "f"(x)); return r;
}
__device__ __forceinline__ uint32_t smem_u32(const void* p) {
    uint32_t a;
    asm("{ .reg .u64 t; cvta.to.shared.u64 t, %1; cvt.u32.u64 %0, t; }" : "=r"(a) : "l"(p));
    return a;
}
__device__ __forceinline__ uint32_t pack_split(float a, float b, uint32_t& lo) {
    __nv_bfloat16 ha = __float2bfloat16(a), hb = __float2bfloat16(b);
    __nv_bfloat16 la = __float2bfloat16(a - __bfloat162float(ha));
    __nv_bfloat16 lb = __float2bfloat16(b - __bfloat162float(hb));
    lo = ((uint32_t)__bfloat16_as_ushort(lb) << 16) | __bfloat16_as_ushort(la);
    return ((uint32_t)__bfloat16_as_ushort(hb) << 16) | __bfloat16_as_ushort(ha);
}

#define LDSM_X4(r0, r1, r2, r3, addr) \
    asm volatile("ldmatrix.sync.aligned.m8n8.x4.shared.b16 {%0,%1,%2,%3}, [%4];" \
                 : "=r"(r0), "=r"(r1), "=r"(r2), "=r"(r3) : "r"(addr))

#define MMA16816(acc, a0, a1, a2, a3, b0, b1) \
    asm volatile("mma.sync.aligned.m16n8k16.row.col.f32.bf16.bf16.f32 " \
                 "{%0,%1,%2,%3}, {%4,%5,%6,%7}, {%8,%9}, {%0,%1,%2,%3};" \
                 : "+f"((acc)[0]), "+f"((acc)[1]), "+f"((acc)[2]), "+f"((acc)[3]) \
                 : "r"(a0), "r"(a1), "r"(a2), "r"(a3), "r"(b0), "r"(b1))

// smem layout: rows padded to 136 bf16 (272 B) -> conflict-free ldmatrix.
#define ROWB 272u
#define WIMGB (128u * ROWB)          // 34816 per W image
#define AIMGB (64u * ROWB)           // 17408 per A image
#define SM_WH 0u
#define SM_WL WIMGB                  // 34816
#define SM_AH (2u * WIMGB)           // 69632
#define SM_AL (SM_AH + AIMGB)        // 87040
#define SM_TOTAL (SM_AL + AIMGB)     // 104448 (102 KB) -> 2 CTAs/SM

// ---------------------------------------------------------------------------
// Kernel 0: build bf16 hi/lo W images (plain [n][k-pair] layout)
// ---------------------------------------------------------------------------
__global__ void prep_w(const float* __restrict__ Win, const float* __restrict__ Wag) {
    int n = blockIdx.x;     // output feature 0..127
    int kp = threadIdx.x;   // k-pair 0..63
    int k0 = kp * 2;
    float a0 = Win[k0 * 128 + n], a1 = Win[(k0 + 1) * 128 + n];
    float b0 = Wag[k0 * 128 + n], b1 = Wag[(k0 + 1) * 128 + n];
    uint32_t alo, blo;
    uint32_t ahi = pack_split(a0, a1, alo);
    uint32_t bhi = pack_split(b0, b1, blo);
    int idx = n * 64 + kp;
    g_wimg[0 * 8192 + idx] = ahi;
    g_wimg[1 * 8192 + idx] = alo;
    g_wimg[2 * 8192 + idx] = bhi;
    g_wimg[3 * 8192 + idx] = blo;
}

// ---------------------------------------------------------------------------
// Kernel 2: scatter-add  g_agg[dst] += g_hw[src]  (one warp per edge)
// ---------------------------------------------------------------------------
__global__ void scatter_kernel(const int* __restrict__ src,
                               const int* __restrict__ dst, int E) {
    int warp = (blockIdx.x * blockDim.x + threadIdx.x) >> 5;
    int lane = threadIdx.x & 31;
    if (warp >= E) return;
    int s = __ldg(&src[warp]);
    int d = __ldg(&dst[warp]);
    const float4 v = __ldg(reinterpret_cast<const float4*>(g_hw + (size_t)s * 128) + lane);
    float* p = g_agg + (size_t)d * 128 + lane * 4;
    asm volatile("red.global.add.v4.f32 [%0], {%1,%2,%3,%4};"
                 :: "l"(p), "f"(v.x), "f"(v.y), "f"(v.z), "f"(v.w)
                 : "memory");
}

// ---------------------------------------------------------------------------
// GEMM (persistent): CTA = 64 rows x 128 cols; warp tile 32x32 (grid 2x4).
// MODE 0: outp = A @ W, and zero g_agg slice    (gemm1: A=h, W=W_aggr pair)
// MODE 1: outp = tanh(A_m @ W + g_agg + m*bin + baggr)  (gemm2: A=x, W=W_in)
// ---------------------------------------------------------------------------
template <int MODE>
__global__ void __launch_bounds__(256, 2) gemm_phase(
    const float* __restrict__ A, const unsigned int* __restrict__ wpair,
    const float* __restrict__ bin, const float* __restrict__ baggr,
    const int* __restrict__ mask, float* __restrict__ outp, int N, int ntiles) {
    extern __shared__ char smem[];
    const uint32_t sbase = smem_u32(smem);
    const int tid = threadIdx.x;
    const int wid = tid >> 5;
    const int lid = tid & 31;

    // ---- copy W hi/lo pair into smem ONCE (persistent CTA) ----
    {
        const uint4* src = reinterpret_cast<const uint4*>(wpair);
#pragma unroll
        for (int it = 0; it < 16; it++) {
            int idx = tid + it * 256;        // 4096 uint4 (2 images)
            int row = idx >> 4;              // 0..255: img*128 + n
            int j = idx & 15;
            int img = row >> 7, n = row & 127;
            *reinterpret_cast<uint4*>(smem + SM_WH + (uint32_t)img * WIMGB +
                                      (uint32_t)n * ROWB + (uint32_t)j * 16) = src[idx];
        }
    }

    // warp tile: rows m0..m0+31, cols n0..n0+31
    const int wr = wid >> 2;       // 0..1
    const int wc = wid & 3;        // 0..3
    const int m0 = wr * 32;
    const int n0 = wc * 32;

    const int l8 = lid & 7;
    const int quad = lid >> 3;
    const uint32_t a_lane_off =
        (uint32_t)((m0 + l8 + (quad & 1) * 8) * ROWB + ((quad >> 1) * 8) * 2);
    const uint32_t b_lane_off =
        (uint32_t)((n0 + l8 + (quad >> 1) * 8) * ROWB + ((quad & 1) * 8) * 2);
    const uint32_t whi = sbase + SM_WH + b_lane_off;
    const uint32_t wlo = sbase + SM_WL + b_lane_off;
    const uint32_t ahb = sbase + SM_AH + a_lane_off;
    const uint32_t alb = sbase + SM_AL + a_lane_off;

    // A-tile loader mapping: thread -> (row 0..63, 32-col chunk)
    const int arow = tid >> 2;
    const int acb = (tid & 3) * 32;

    // epilogue mapping
    const int tq = lid >> 2;   // 0..7
    const int t4 = lid & 3;    // 0..3

    uint32_t fa[16], fbh[8], fbl[8];

    for (int tile = blockIdx.x; tile < ntiles; tile += gridDim.x) {
        const int row0 = tile * 64;
        const int rg = row0 + arow;
        const bool ok = (rg < N);

        // ---- load A rows (global) ----
        float4 av[8];
        {
            const float4* as =
                reinterpret_cast<const float4*>(A + (size_t)(ok ? rg : 0) * 128 + acb);
#pragma unroll
            for (int j = 0; j < 8; j++)
                av[j] = ok ? __ldg(as + j) : make_float4(0.f, 0.f, 0.f, 0.f);
        }
        float mrow = 1.f;
        if (MODE == 1)
            mrow = (ok && (__ldg(&mask[ok ? rg : 0]) != 0)) ? 1.f : 0.f;

        __syncthreads();  // previous tile's LDSMs complete; W copy ordered (tile 0)

        // ---- convert + store A tile (mask folded for MODE 1) ----
#pragma unroll
        for (int j = 0; j < 8; j++) {
            float4 v = av[j];
            if (MODE == 1) { v.x *= mrow; v.y *= mrow; v.z *= mrow; v.w *= mrow; }
            uint32_t lo01, lo23;
            uint32_t hi01 = pack_split(v.x, v.y, lo01);
            uint32_t hi23 = pack_split(v.z, v.w, lo23);
            uint32_t off = (uint32_t)(arow * ROWB + (acb + 4 * j) * 2);
            *reinterpret_cast<uint32_t*>(smem + SM_AH + off) = hi01;
            *reinterpret_cast<uint32_t*>(smem + SM_AH + off + 4) = hi23;
            *reinterpret_cast<uint32_t*>(smem + SM_AL + off) = lo01;
            *reinterpret_cast<uint32_t*>(smem + SM_AL + off + 4) = lo23;
        }

        // ---- MODE 0: zero this tile's g_agg slice (hidden under MMAs) ----
        if (MODE == 0) {
            float4* zp = reinterpret_cast<float4*>(g_agg) + (size_t)tile * 2048;
            const float4 z = make_float4(0.f, 0.f, 0.f, 0.f);
#pragma unroll
            for (int j = 0; j < 8; j++) zp[tid + j * 256] = z;
        }
        __syncthreads();

        // ---- accumulators ----
        float acc[2][4][4];
#pragma unroll
        for (int mt = 0; mt < 2; mt++)
#pragma unroll
            for (int nt = 0; nt < 4; nt++) {
                acc[mt][nt][0] = acc[mt][nt][1] = acc[mt][nt][2] = acc[mt][nt][3] = 0.f;
            }

        // ---- k-loop (8 k-steps), single frag buffer; cross-warp hiding ----
#pragma unroll
        for (int ks = 0; ks < 8; ks++) {
            const uint32_t kb = (uint32_t)(ks * 32);
            LDSM_X4(fa[0], fa[1], fa[2], fa[3], ahb + kb);
            LDSM_X4(fa[4], fa[5], fa[6], fa[7], ahb + 16 * ROWB + kb);
            LDSM_X4(fa[8], fa[9], fa[10], fa[11], alb + kb);
            LDSM_X4(fa[12], fa[13], fa[14], fa[15], alb + 16 * ROWB + kb);
            LDSM_X4(fbh[0], fbh[1], fbh[2], fbh[3], whi + kb);
            LDSM_X4(fbh[4], fbh[5], fbh[6], fbh[7], whi + 16 * ROWB + kb);
            LDSM_X4(fbl[0], fbl[1], fbl[2], fbl[3], wlo + kb);
            LDSM_X4(fbl[4], fbl[5], fbl[6], fbl[7], wlo + 16 * ROWB + kb);
#pragma unroll
            for (int nt = 0; nt < 4; nt++) {
                MMA16816(acc[0][nt], fa[0], fa[1], fa[2], fa[3], fbh[2 * nt], fbh[2 * nt + 1]);
                MMA16816(acc[1][nt], fa[4], fa[5], fa[6], fa[7], fbh[2 * nt], fbh[2 * nt + 1]);
            }
#pragma unroll
            for (int nt = 0; nt < 4; nt++) {
                MMA16816(acc[0][nt], fa[8], fa[9], fa[10], fa[11], fbh[2 * nt], fbh[2 * nt + 1]);
                MMA16816(acc[1][nt], fa[12], fa[13], fa[14], fa[15], fbh[2 * nt], fbh[2 * nt + 1]);
            }
#pragma unroll
            for (int nt = 0; nt < 4; nt++) {
                MMA16816(acc[0][nt], fa[0], fa[1], fa[2], fa[3], fbl[2 * nt], fbl[2 * nt + 1]);
                MMA16816(acc[1][nt], fa[4], fa[5], fa[6], fa[7], fbl[2 * nt], fbl[2 * nt + 1]);
            }
        }

        // ---- epilogue ----
#pragma unroll
        for (int mt = 0; mt < 2; mt++) {
            const int r1 = row0 + m0 + mt * 16 + tq;
            const int r2 = r1 + 8;
            if (MODE == 0) {
#pragma unroll
                for (int nt = 0; nt < 4; nt++) {
                    const int c = n0 + nt * 8 + 2 * t4;
                    if (r1 < N) {
                        float2 o; o.x = acc[mt][nt][0]; o.y = acc[mt][nt][1];
                        *reinterpret_cast<float2*>(&outp[(size_t)r1 * 128 + c]) = o;
                    }
                    if (r2 < N) {
                        float2 o; o.x = acc[mt][nt][2]; o.y = acc[mt][nt][3];
                        *reinterpret_cast<float2*>(&outp[(size_t)r2 * 128 + c]) = o;
                    }
                }
            } else {
                const float m1 = (r1 < N && __ldg(&mask[r1 < N ? r1 : 0]) != 0) ? 1.f : 0.f;
                const float m2 = (r2 < N && __ldg(&mask[r2 < N ? r2 : 0]) != 0) ? 1.f : 0.f;
#pragma unroll
                for (int nt = 0; nt < 4; nt++) {
                    const int c = n0 + nt * 8 + 2 * t4;
                    const float bi0 = __ldg(&bin[c]), bi1 = __ldg(&bin[c + 1]);
                    const float ba0 = __ldg(&baggr[c]), ba1 = __ldg(&baggr[c + 1]);
                    if (r1 < N) {
                        float2 ag = *reinterpret_cast<const float2*>(
                            &g_agg[(size_t)r1 * 128 + c]);
                        float2 o;
                        o.x = tanh_fast(acc[mt][nt][0] + ag.x + m1 * bi0 + ba0);
                        o.y = tanh_fast(acc[mt][nt][1] + ag.y + m1 * bi1 + ba1);
                        *reinterpret_cast<float2*>(&outp[(size_t)r1 * 128 + c]) = o;
                    }
                    if (r2 < N) {
                        float2 ag = *reinterpret_cast<const float2*>(
                            &g_agg[(size_t)r2 * 128 + c]);
                        float2 o;
                        o.x = tanh_fast(acc[mt][nt][2] + ag.x + m2 * bi0 + ba0);
                        o.y = tanh_fast(acc[mt][nt][3] + ag.y + m2 * bi1 + ba1);
                        *reinterpret_cast<float2*>(&outp[(size_t)r2 * 128 + c]) = o;
                    }
                }
            }
        }
    }
}

// ---------------------------------------------------------------------------
// Launch
// ---------------------------------------------------------------------------
extern "C" void kernel_launch(void* const* d_in, const int* in_sizes, int n_in,
                              void* d_out, int out_size) {
    const float* x     = (const float*)d_in[0];
    const float* h     = (const float*)d_in[1];
    const float* Win   = (const float*)d_in[2];
    const float* bin   = (const float*)d_in[3];
    const float* Waggr = (const float*)d_in[4];
    const float* baggr = (const float*)d_in[5];
    const int* mask    = (const int*)d_in[6];
    const int* esrc    = (const int*)d_in[7];
    const int* edst    = (const int*)d_in[8];
    float* out = (float*)d_out;

    const int N = in_sizes[0] / 128;
    const int E = in_sizes[7];
    const int ntiles = (N + 63) / 64;

    static int smem_set = 0;
    if (!smem_set) {
        cudaFuncSetAttribute(gemm_phase<0>, cudaFuncAttributeMaxDynamicSharedMemorySize,
                             (int)SM_TOTAL);
        cudaFuncSetAttribute(gemm_phase<1>, cudaFuncAttributeMaxDynamicSharedMemorySize,
                             (int)SM_TOTAL);
        smem_set = 1;
    }

    unsigned int* wimg_dev = nullptr;
    cudaGetSymbolAddress((void**)&wimg_dev, g_wimg);
    float* hw_dev = nullptr;
    cudaGetSymbolAddress((void**)&hw_dev, g_hw);

    prep_w<<<128, 64>>>(Win, Waggr);
    // gemm1: hW = h @ W_aggr (images 2,3); also zeroes g_agg
    gemm_phase<0><<<296, 256, SM_TOTAL>>>(h, wimg_dev + 2 * 8192, nullptr, nullptr,
                                          nullptr, hw_dev, N, ntiles);
    // scatter: g_agg[dst] += hW[src]
    scatter_kernel<<<(E + 7) / 8, 256>>>(esrc, edst, E);
    // gemm2: out = tanh(x_m @ W_in + g_agg + m*b_in + b_aggr)   (images 0,1)
    gemm_phase<1><<<296, 256, SM_TOTAL>>>(x, wimg_dev, bin, baggr, mask, out, N,
                                          ntiles);
}

// round 11
// speedup vs baseline: 1.2357x; 1.2357x over previous
#include <cuda_runtime.h>
#include <cuda_bf16.h>
#include <cstdint>
#include <cstddef>

// ---------------------------------------------------------------------------
// TreeRNNCell: out = tanh( mask*(x@W_in + b_in) + segsum(h[src]->dst)@W_aggr + b_aggr )
// N = 500000, E = 500000, X = H = 128.
//
// R10: R9 split structure +
//   - coalesced A-tile loads (linear float4 mapping: nL=4/instr, was 32)
//   - next-tile A prefetch issued before the k-loop (latency hidden under MMA)
// Pipeline: prep_w -> gemm1(hW=h@W_aggr, zero agg) -> scatter(hW) -> gemm2.
// ---------------------------------------------------------------------------

#define MAXN 500000
#define NPAD 500032  // ntiles*64 rounding for fused agg-zero
__device__ float g_agg[(size_t)NPAD * 128];
__device__ float g_hw[(size_t)MAXN * 128];
// 4 images: [Win_hi, Win_lo, Wag_hi, Wag_lo], each [128n][64 uint] = bf16x2[n][k]
__device__ __align__(16) unsigned int g_wimg[4 * 8192];

__device__ __forceinline__ float tanh_fast(float x) {
    float r; asm("tanh.approx.f32 %0, %1;" : "=f"(r) : "f"(x)); return r;
}
__device__ __forceinline__ uint32_t smem_u32(const void* p) {
    uint32_t a;
    asm("{ .reg .u64 t; cvta.to.shared.u64 t, %1; cvt.u32.u64 %0, t; }" : "=r"(a) : "l"(p));
    return a;
}
__device__ __forceinline__ uint32_t pack_split(float a, float b, uint32_t& lo) {
    __nv_bfloat16 ha = __float2bfloat16(a), hb = __float2bfloat16(b);
    __nv_bfloat16 la = __float2bfloat16(a - __bfloat162float(ha));
    __nv_bfloat16 lb = __float2bfloat16(b - __bfloat162float(hb));
    lo = ((uint32_t)__bfloat16_as_ushort(lb) << 16) | __bfloat16_as_ushort(la);
    return ((uint32_t)__bfloat16_as_ushort(hb) << 16) | __bfloat16_as_ushort(ha);
}

#define LDSM_X4(r0, r1, r2, r3, addr) \
    asm volatile("ldmatrix.sync.aligned.m8n8.x4.shared.b16 {%0,%1,%2,%3}, [%4];" \
                 : "=r"(r0), "=r"(r1), "=r"(r2), "=r"(r3) : "r"(addr))

#define MMA16816(acc, a0, a1, a2, a3, b0, b1) \
    asm volatile("mma.sync.aligned.m16n8k16.row.col.f32.bf16.bf16.f32 " \
                 "{%0,%1,%2,%3}, {%4,%5,%6,%7}, {%8,%9}, {%0,%1,%2,%3};" \
                 : "+f"((acc)[0]), "+f"((acc)[1]), "+f"((acc)[2]), "+f"((acc)[3]) \
                 : "r"(a0), "r"(a1), "r"(a2), "r"(a3), "r"(b0), "r"(b1))

// smem layout: rows padded to 136 bf16 (272 B) -> conflict-free ldmatrix.
#define ROWB 272u
#define WIMGB (128u * ROWB)          // 34816 per W image
#define AIMGB (64u * ROWB)           // 17408 per A image
#define SM_WH 0u
#define SM_WL WIMGB                  // 34816
#define SM_AH (2u * WIMGB)           // 69632
#define SM_AL (SM_AH + AIMGB)        // 87040
#define SM_TOTAL (SM_AL + AIMGB)     // 104448 (102 KB) -> 2 CTAs/SM

// ---------------------------------------------------------------------------
// Kernel 0: build bf16 hi/lo W images (plain [n][k-pair] layout)
// ---------------------------------------------------------------------------
__global__ void prep_w(const float* __restrict__ Win, const float* __restrict__ Wag) {
    int n = blockIdx.x;     // output feature 0..127
    int kp = threadIdx.x;   // k-pair 0..63
    int k0 = kp * 2;
    float a0 = Win[k0 * 128 + n], a1 = Win[(k0 + 1) * 128 + n];
    float b0 = Wag[k0 * 128 + n], b1 = Wag[(k0 + 1) * 128 + n];
    uint32_t alo, blo;
    uint32_t ahi = pack_split(a0, a1, alo);
    uint32_t bhi = pack_split(b0, b1, blo);
    int idx = n * 64 + kp;
    g_wimg[0 * 8192 + idx] = ahi;
    g_wimg[1 * 8192 + idx] = alo;
    g_wimg[2 * 8192 + idx] = bhi;
    g_wimg[3 * 8192 + idx] = blo;
}

// ---------------------------------------------------------------------------
// Kernel 2: scatter-add  g_agg[dst] += g_hw[src]  (one warp per edge)
// ---------------------------------------------------------------------------
__global__ void scatter_kernel(const int* __restrict__ src,
                               const int* __restrict__ dst, int E) {
    int warp = (blockIdx.x * blockDim.x + threadIdx.x) >> 5;
    int lane = threadIdx.x & 31;
    if (warp >= E) return;
    int s = __ldg(&src[warp]);
    int d = __ldg(&dst[warp]);
    const float4 v = __ldg(reinterpret_cast<const float4*>(g_hw + (size_t)s * 128) + lane);
    float* p = g_agg + (size_t)d * 128 + lane * 4;
    asm volatile("red.global.add.v4.f32 [%0], {%1,%2,%3,%4};"
                 :: "l"(p), "f"(v.x), "f"(v.y), "f"(v.z), "f"(v.w)
                 : "memory");
}

// ---------------------------------------------------------------------------
// GEMM (persistent): CTA = 64 rows x 128 cols; warp tile 32x32 (grid 2x4).
// MODE 0: outp = A @ W, and zero g_agg slice    (gemm1: A=h, W=W_aggr pair)
// MODE 1: outp = tanh(A_m @ W + g_agg + m*bin + baggr)  (gemm2: A=x, W=W_in)
// A loads: linear float4 mapping (fully coalesced); next-tile prefetch
// issued before the k-loop so DRAM latency hides under MMA + epilogue.
// ---------------------------------------------------------------------------
template <int MODE>
__global__ void __launch_bounds__(256, 2) gemm_phase(
    const float* __restrict__ A, const unsigned int* __restrict__ wpair,
    const float* __restrict__ bin, const float* __restrict__ baggr,
    const int* __restrict__ mask, float* __restrict__ outp, int N, int ntiles) {
    extern __shared__ char smem[];
    const uint32_t sbase = smem_u32(smem);
    const int tid = threadIdx.x;
    const int wid = tid >> 5;
    const int lid = tid & 31;

    const float4* A4 = reinterpret_cast<const float4*>(A);
    const long long max4 = (long long)N * 32 - 1;  // last valid float4 index

    // ---- prefetch A tile for first assigned tile (coalesced linear map) ----
    float4 av[8];
    float m8[8];
    {
        const long long base = (long long)blockIdx.x * 2048;
#pragma unroll
        for (int j = 0; j < 8; j++) {
            long long gi = base + (tid + 256 * j);
            av[j] = __ldg(A4 + (gi <= max4 ? gi : max4));
            if (MODE == 1) {
                int row = (int)(gi >> 5);
                m8[j] = (row < N && __ldg(&mask[row < N ? row : 0]) != 0) ? 1.f : 0.f;
            }
        }
    }

    // ---- copy W hi/lo pair into smem ONCE (persistent CTA) ----
    {
        const uint4* src = reinterpret_cast<const uint4*>(wpair);
#pragma unroll
        for (int it = 0; it < 16; it++) {
            int idx = tid + it * 256;        // 4096 uint4 (2 images)
            int row = idx >> 4;              // 0..255: img*128 + n
            int j = idx & 15;
            int img = row >> 7, n = row & 127;
            *reinterpret_cast<uint4*>(smem + SM_WH + (uint32_t)img * WIMGB +
                                      (uint32_t)n * ROWB + (uint32_t)j * 16) = src[idx];
        }
    }

    // warp tile: rows m0..m0+31, cols n0..n0+31
    const int wr = wid >> 2;       // 0..1
    const int wc = wid & 3;        // 0..3
    const int m0 = wr * 32;
    const int n0 = wc * 32;

    const int l8 = lid & 7;
    const int quad = lid >> 3;
    const uint32_t a_lane_off =
        (uint32_t)((m0 + l8 + (quad & 1) * 8) * ROWB + ((quad >> 1) * 8) * 2);
    const uint32_t b_lane_off =
        (uint32_t)((n0 + l8 + (quad >> 1) * 8) * ROWB + ((quad & 1) * 8) * 2);
    const uint32_t whi = sbase + SM_WH + b_lane_off;
    const uint32_t wlo = sbase + SM_WL + b_lane_off;
    const uint32_t ahb = sbase + SM_AH + a_lane_off;
    const uint32_t alb = sbase + SM_AL + a_lane_off;

    // epilogue mapping
    const int tq = lid >> 2;   // 0..7
    const int t4 = lid & 3;    // 0..3

    uint32_t fa[16], fbh[8], fbl[8];

    for (int tile = blockIdx.x; tile < ntiles; tile += gridDim.x) {
        const int row0 = tile * 64;

        __syncthreads();  // previous tile's LDSMs complete; W copy ordered (tile 0)

        // ---- convert + store A tile from prefetched regs (mask folded) ----
#pragma unroll
        for (int j = 0; j < 8; j++) {
            int idx = tid + 256 * j;
            int row_l = idx >> 5;
            int c4 = idx & 31;
            float4 v = av[j];
            if (MODE == 1) { v.x *= m8[j]; v.y *= m8[j]; v.z *= m8[j]; v.w *= m8[j]; }
            uint32_t lo01, lo23;
            uint32_t hi01 = pack_split(v.x, v.y, lo01);
            uint32_t hi23 = pack_split(v.z, v.w, lo23);
            uint32_t off = (uint32_t)(row_l * ROWB + c4 * 8);
            uint2 hh; hh.x = hi01; hh.y = hi23;
            uint2 ll; ll.x = lo01; ll.y = lo23;
            *reinterpret_cast<uint2*>(smem + SM_AH + off) = hh;
            *reinterpret_cast<uint2*>(smem + SM_AL + off) = ll;
        }

        // ---- MODE 0: zero this tile's g_agg slice (coalesced) ----
        if (MODE == 0) {
            float4* zp = reinterpret_cast<float4*>(g_agg) + (size_t)tile * 2048;
            const float4 z = make_float4(0.f, 0.f, 0.f, 0.f);
#pragma unroll
            for (int j = 0; j < 8; j++) zp[tid + j * 256] = z;
        }
        __syncthreads();

        // ---- prefetch NEXT tile's A (in flight during MMA + epilogue) ----
        {
            const int tn = tile + gridDim.x;
            if (tn < ntiles) {
                const long long base = (long long)tn * 2048;
#pragma unroll
                for (int j = 0; j < 8; j++) {
                    long long gi = base + (tid + 256 * j);
                    av[j] = __ldg(A4 + (gi <= max4 ? gi : max4));
                    if (MODE == 1) {
                        int row = (int)(gi >> 5);
                        m8[j] = (row < N && __ldg(&mask[row < N ? row : 0]) != 0)
                                    ? 1.f : 0.f;
                    }
                }
            }
        }

        // ---- accumulators ----
        float acc[2][4][4];
#pragma unroll
        for (int mt = 0; mt < 2; mt++)
#pragma unroll
            for (int nt = 0; nt < 4; nt++) {
                acc[mt][nt][0] = acc[mt][nt][1] = acc[mt][nt][2] = acc[mt][nt][3] = 0.f;
            }

        // ---- k-loop (8 k-steps), single frag buffer; cross-warp hiding ----
#pragma unroll
        for (int ks = 0; ks < 8; ks++) {
            const uint32_t kb = (uint32_t)(ks * 32);
            LDSM_X4(fa[0], fa[1], fa[2], fa[3], ahb + kb);
            LDSM_X4(fa[4], fa[5], fa[6], fa[7], ahb + 16 * ROWB + kb);
            LDSM_X4(fa[8], fa[9], fa[10], fa[11], alb + kb);
            LDSM_X4(fa[12], fa[13], fa[14], fa[15], alb + 16 * ROWB + kb);
            LDSM_X4(fbh[0], fbh[1], fbh[2], fbh[3], whi + kb);
            LDSM_X4(fbh[4], fbh[5], fbh[6], fbh[7], whi + 16 * ROWB + kb);
            LDSM_X4(fbl[0], fbl[1], fbl[2], fbl[3], wlo + kb);
            LDSM_X4(fbl[4], fbl[5], fbl[6], fbl[7], wlo + 16 * ROWB + kb);
#pragma unroll
            for (int nt = 0; nt < 4; nt++) {
                MMA16816(acc[0][nt], fa[0], fa[1], fa[2], fa[3], fbh[2 * nt], fbh[2 * nt + 1]);
                MMA16816(acc[1][nt], fa[4], fa[5], fa[6], fa[7], fbh[2 * nt], fbh[2 * nt + 1]);
            }
#pragma unroll
            for (int nt = 0; nt < 4; nt++) {
                MMA16816(acc[0][nt], fa[8], fa[9], fa[10], fa[11], fbh[2 * nt], fbh[2 * nt + 1]);
                MMA16816(acc[1][nt], fa[12], fa[13], fa[14], fa[15], fbh[2 * nt], fbh[2 * nt + 1]);
            }
#pragma unroll
            for (int nt = 0; nt < 4; nt++) {
                MMA16816(acc[0][nt], fa[0], fa[1], fa[2], fa[3], fbl[2 * nt], fbl[2 * nt + 1]);
                MMA16816(acc[1][nt], fa[4], fa[5], fa[6], fa[7], fbl[2 * nt], fbl[2 * nt + 1]);
            }
        }

        // ---- epilogue ----
#pragma unroll
        for (int mt = 0; mt < 2; mt++) {
            const int r1 = row0 + m0 + mt * 16 + tq;
            const int r2 = r1 + 8;
            if (MODE == 0) {
#pragma unroll
                for (int nt = 0; nt < 4; nt++) {
                    const int c = n0 + nt * 8 + 2 * t4;
                    if (r1 < N) {
                        float2 o; o.x = acc[mt][nt][0]; o.y = acc[mt][nt][1];
                        *reinterpret_cast<float2*>(&outp[(size_t)r1 * 128 + c]) = o;
                    }
                    if (r2 < N) {
                        float2 o; o.x = acc[mt][nt][2]; o.y = acc[mt][nt][3];
                        *reinterpret_cast<float2*>(&outp[(size_t)r2 * 128 + c]) = o;
                    }
                }
            } else {
                const float m1 = (r1 < N && __ldg(&mask[r1 < N ? r1 : 0]) != 0) ? 1.f : 0.f;
                const float m2 = (r2 < N && __ldg(&mask[r2 < N ? r2 : 0]) != 0) ? 1.f : 0.f;
#pragma unroll
                for (int nt = 0; nt < 4; nt++) {
                    const int c = n0 + nt * 8 + 2 * t4;
                    const float bi0 = __ldg(&bin[c]), bi1 = __ldg(&bin[c + 1]);
                    const float ba0 = __ldg(&baggr[c]), ba1 = __ldg(&baggr[c + 1]);
                    if (r1 < N) {
                        float2 ag = *reinterpret_cast<const float2*>(
                            &g_agg[(size_t)r1 * 128 + c]);
                        float2 o;
                        o.x = tanh_fast(acc[mt][nt][0] + ag.x + m1 * bi0 + ba0);
                        o.y = tanh_fast(acc[mt][nt][1] + ag.y + m1 * bi1 + ba1);
                        *reinterpret_cast<float2*>(&outp[(size_t)r1 * 128 + c]) = o;
                    }
                    if (r2 < N) {
                        float2 ag = *reinterpret_cast<const float2*>(
                            &g_agg[(size_t)r2 * 128 + c]);
                        float2 o;
                        o.x = tanh_fast(acc[mt][nt][2] + ag.x + m2 * bi0 + ba0);
                        o.y = tanh_fast(acc[mt][nt][3] + ag.y + m2 * bi1 + ba1);
                        *reinterpret_cast<float2*>(&outp[(size_t)r2 * 128 + c]) = o;
                    }
                }
            }
        }
    }
}

// ---------------------------------------------------------------------------
// Launch
// ---------------------------------------------------------------------------
extern "C" void kernel_launch(void* const* d_in, const int* in_sizes, int n_in,
                              void* d_out, int out_size) {
    const float* x     = (const float*)d_in[0];
    const float* h     = (const float*)d_in[1];
    const float* Win   = (const float*)d_in[2];
    const float* bin   = (const float*)d_in[3];
    const float* Waggr = (const float*)d_in[4];
    const float* baggr = (const float*)d_in[5];
    const int* mask    = (const int*)d_in[6];
    const int* esrc    = (const int*)d_in[7];
    const int* edst    = (const int*)d_in[8];
    float* out = (float*)d_out;

    const int N = in_sizes[0] / 128;
    const int E = in_sizes[7];
    const int ntiles = (N + 63) / 64;

    static int smem_set = 0;
    if (!smem_set) {
        cudaFuncSetAttribute(gemm_phase<0>, cudaFuncAttributeMaxDynamicSharedMemorySize,
                             (int)SM_TOTAL);
        cudaFuncSetAttribute(gemm_phase<1>, cudaFuncAttributeMaxDynamicSharedMemorySize,
                             (int)SM_TOTAL);
        smem_set = 1;
    }

    unsigned int* wimg_dev = nullptr;
    cudaGetSymbolAddress((void**)&wimg_dev, g_wimg);
    float* hw_dev = nullptr;
    cudaGetSymbolAddress((void**)&hw_dev, g_hw);

    prep_w<<<128, 64>>>(Win, Waggr);
    // gemm1: hW = h @ W_aggr (images 2,3); also zeroes g_agg
    gemm_phase<0><<<296, 256, SM_TOTAL>>>(h, wimg_dev + 2 * 8192, nullptr, nullptr,
                                          nullptr, hw_dev, N, ntiles);
    // scatter: g_agg[dst] += hW[src]
    scatter_kernel<<<(E + 7) / 8, 256>>>(esrc, edst, E);
    // gemm2: out = tanh(x_m @ W_in + g_agg + m*b_in + b_aggr)   (images 0,1)
    gemm_phase<1><<<296, 256, SM_TOTAL>>>(x, wimg_dev, bin, baggr, mask, out, N,
                                          ntiles);
}

// round 12
// speedup vs baseline: 1.2800x; 1.0358x over previous
#include <cuda_runtime.h>
#include <cuda_bf16.h>
#include <cstdint>
#include <cstddef>

// ---------------------------------------------------------------------------
// TreeRNNCell: out = tanh( mask*(x@W_in + b_in) + segsum(h[src]->dst)@W_aggr + b_aggr )
// N = 500000, E = 500000, X = H = 128.
//
// R11: R10 + epilogue staged through smem (reusing the dead A region after
// the k-loop) so all epilogue global traffic is linear float4 (LDG.128 /
// STG.128, 4 lines per instr, 8-deep MLP on the agg loads).
// Pipeline: prep_w -> gemm1(hW=h@W_aggr, zero agg) -> scatter(hW) -> gemm2.
// ---------------------------------------------------------------------------

#define MAXN 500000
#define NPAD 500032  // ntiles*64 rounding for fused agg-zero
__device__ float g_agg[(size_t)NPAD * 128];
__device__ float g_hw[(size_t)MAXN * 128];
// 4 images: [Win_hi, Win_lo, Wag_hi, Wag_lo], each [128n][64 uint] = bf16x2[n][k]
__device__ __align__(16) unsigned int g_wimg[4 * 8192];

__device__ __forceinline__ float tanh_fast(float x) {
    float r; asm("tanh.approx.f32 %0, %1;" : "=f"(r) : "f"(x)); return r;
}
__device__ __forceinline__ uint32_t smem_u32(const void* p) {
    uint32_t a;
    asm("{ .reg .u64 t; cvta.to.shared.u64 t, %1; cvt.u32.u64 %0, t; }" : "=r"(a) : "l"(p));
    return a;
}
__device__ __forceinline__ uint32_t pack_split(float a, float b, uint32_t& lo) {
    __nv_bfloat16 ha = __float2bfloat16(a), hb = __float2bfloat16(b);
    __nv_bfloat16 la = __float2bfloat16(a - __bfloat162float(ha));
    __nv_bfloat16 lb = __float2bfloat16(b - __bfloat162float(hb));
    lo = ((uint32_t)__bfloat16_as_ushort(lb) << 16) | __bfloat16_as_ushort(la);
    return ((uint32_t)__bfloat16_as_ushort(hb) << 16) | __bfloat16_as_ushort(ha);
}

#define LDSM_X4(r0, r1, r2, r3, addr) \
    asm volatile("ldmatrix.sync.aligned.m8n8.x4.shared.b16 {%0,%1,%2,%3}, [%4];" \
                 : "=r"(r0), "=r"(r1), "=r"(r2), "=r"(r3) : "r"(addr))

#define MMA16816(acc, a0, a1, a2, a3, b0, b1) \
    asm volatile("mma.sync.aligned.m16n8k16.row.col.f32.bf16.bf16.f32 " \
                 "{%0,%1,%2,%3}, {%4,%5,%6,%7}, {%8,%9}, {%0,%1,%2,%3};" \
                 : "+f"((acc)[0]), "+f"((acc)[1]), "+f"((acc)[2]), "+f"((acc)[3]) \
                 : "r"(a0), "r"(a1), "r"(a2), "r"(a3), "r"(b0), "r"(b1))

// smem layout: rows padded to 136 bf16 (272 B) -> conflict-free ldmatrix.
#define ROWB 272u
#define ROWF 132                     // epilogue f32 stage row stride (528 B)
#define WIMGB (128u * ROWB)          // 34816 per W image
#define AIMGB (64u * ROWB)           // 17408 per A image
#define SM_WH 0u
#define SM_WL WIMGB                  // 34816
#define SM_AH (2u * WIMGB)           // 69632
#define SM_AL (SM_AH + AIMGB)        // 87040
#define SM_TOTAL (SM_AL + AIMGB)     // 104448 (102 KB) -> 2 CTAs/SM
// epilogue stage overlays SM_AH..: 64*132*4 = 33792 <= 2*AIMGB = 34816  OK

// ---------------------------------------------------------------------------
// Kernel 0: build bf16 hi/lo W images (plain [n][k-pair] layout)
// ---------------------------------------------------------------------------
__global__ void prep_w(const float* __restrict__ Win, const float* __restrict__ Wag) {
    int n = blockIdx.x;     // output feature 0..127
    int kp = threadIdx.x;   // k-pair 0..63
    int k0 = kp * 2;
    float a0 = Win[k0 * 128 + n], a1 = Win[(k0 + 1) * 128 + n];
    float b0 = Wag[k0 * 128 + n], b1 = Wag[(k0 + 1) * 128 + n];
    uint32_t alo, blo;
    uint32_t ahi = pack_split(a0, a1, alo);
    uint32_t bhi = pack_split(b0, b1, blo);
    int idx = n * 64 + kp;
    g_wimg[0 * 8192 + idx] = ahi;
    g_wimg[1 * 8192 + idx] = alo;
    g_wimg[2 * 8192 + idx] = bhi;
    g_wimg[3 * 8192 + idx] = blo;
}

// ---------------------------------------------------------------------------
// Kernel 2: scatter-add  g_agg[dst] += g_hw[src]  (one warp per edge)
// ---------------------------------------------------------------------------
__global__ void scatter_kernel(const int* __restrict__ src,
                               const int* __restrict__ dst, int E) {
    int warp = (blockIdx.x * blockDim.x + threadIdx.x) >> 5;
    int lane = threadIdx.x & 31;
    if (warp >= E) return;
    int s = __ldg(&src[warp]);
    int d = __ldg(&dst[warp]);
    const float4 v = __ldg(reinterpret_cast<const float4*>(g_hw + (size_t)s * 128) + lane);
    float* p = g_agg + (size_t)d * 128 + lane * 4;
    asm volatile("red.global.add.v4.f32 [%0], {%1,%2,%3,%4};"
                 :: "l"(p), "f"(v.x), "f"(v.y), "f"(v.z), "f"(v.w)
                 : "memory");
}

// ---------------------------------------------------------------------------
// GEMM (persistent): CTA = 64 rows x 128 cols; warp tile 32x32 (grid 2x4).
// MODE 0: outp = A @ W, and zero g_agg slice    (gemm1: A=h, W=W_aggr pair)
// MODE 1: outp = tanh(A_m @ W + g_agg + m*bin + baggr)  (gemm2: A=x, W=W_in)
// Epilogue: acc -> smem stage (dead A region) -> linear float4 global.
// ---------------------------------------------------------------------------
template <int MODE>
__global__ void __launch_bounds__(256, 2) gemm_phase(
    const float* __restrict__ A, const unsigned int* __restrict__ wpair,
    const float* __restrict__ bin, const float* __restrict__ baggr,
    const int* __restrict__ mask, float* __restrict__ outp, int N, int ntiles) {
    extern __shared__ char smem[];
    const uint32_t sbase = smem_u32(smem);
    float* epi = reinterpret_cast<float*>(smem + SM_AH);  // post-k-loop overlay
    const int tid = threadIdx.x;
    const int wid = tid >> 5;
    const int lid = tid & 31;

    const float4* A4 = reinterpret_cast<const float4*>(A);
    const float4* agg4 = reinterpret_cast<const float4*>(g_agg);
    const float4* bin4 = reinterpret_cast<const float4*>(bin);
    const float4* bag4 = reinterpret_cast<const float4*>(baggr);
    const long long max4 = (long long)N * 32 - 1;  // last valid float4 index

    // ---- prefetch A tile for first assigned tile (coalesced linear map) ----
    float4 av[8];
    float m8[8];
    {
        const long long base = (long long)blockIdx.x * 2048;
#pragma unroll
        for (int j = 0; j < 8; j++) {
            long long gi = base + (tid + 256 * j);
            av[j] = __ldg(A4 + (gi <= max4 ? gi : max4));
            if (MODE == 1) {
                int row = (int)(gi >> 5);
                m8[j] = (row < N && __ldg(&mask[row < N ? row : 0]) != 0) ? 1.f : 0.f;
            }
        }
    }

    // ---- copy W hi/lo pair into smem ONCE (persistent CTA) ----
    {
        const uint4* src = reinterpret_cast<const uint4*>(wpair);
#pragma unroll
        for (int it = 0; it < 16; it++) {
            int idx = tid + it * 256;        // 4096 uint4 (2 images)
            int row = idx >> 4;              // 0..255: img*128 + n
            int j = idx & 15;
            int img = row >> 7, n = row & 127;
            *reinterpret_cast<uint4*>(smem + SM_WH + (uint32_t)img * WIMGB +
                                      (uint32_t)n * ROWB + (uint32_t)j * 16) = src[idx];
        }
    }

    // warp tile: rows m0..m0+31, cols n0..n0+31
    const int wr = wid >> 2;       // 0..1
    const int wc = wid & 3;        // 0..3
    const int m0 = wr * 32;
    const int n0 = wc * 32;

    const int l8 = lid & 7;
    const int quad = lid >> 3;
    const uint32_t a_lane_off =
        (uint32_t)((m0 + l8 + (quad & 1) * 8) * ROWB + ((quad >> 1) * 8) * 2);
    const uint32_t b_lane_off =
        (uint32_t)((n0 + l8 + (quad >> 1) * 8) * ROWB + ((quad & 1) * 8) * 2);
    const uint32_t whi = sbase + SM_WH + b_lane_off;
    const uint32_t wlo = sbase + SM_WL + b_lane_off;
    const uint32_t ahb = sbase + SM_AH + a_lane_off;
    const uint32_t alb = sbase + SM_AL + a_lane_off;

    // acc->stage mapping
    const int tq = lid >> 2;   // 0..7
    const int t4 = lid & 3;    // 0..3

    uint32_t fa[16], fbh[8], fbl[8];

    for (int tile = blockIdx.x; tile < ntiles; tile += gridDim.x) {
        const int row0 = tile * 64;

        __syncthreads();  // epilogue stage reads done; W copy ordered (tile 0)

        // ---- convert + store A tile from prefetched regs (mask folded) ----
#pragma unroll
        for (int j = 0; j < 8; j++) {
            int idx = tid + 256 * j;
            int row_l = idx >> 5;
            int c4 = idx & 31;
            float4 v = av[j];
            if (MODE == 1) { v.x *= m8[j]; v.y *= m8[j]; v.z *= m8[j]; v.w *= m8[j]; }
            uint32_t lo01, lo23;
            uint32_t hi01 = pack_split(v.x, v.y, lo01);
            uint32_t hi23 = pack_split(v.z, v.w, lo23);
            uint32_t off = (uint32_t)(row_l * ROWB + c4 * 8);
            uint2 hh; hh.x = hi01; hh.y = hi23;
            uint2 ll; ll.x = lo01; ll.y = lo23;
            *reinterpret_cast<uint2*>(smem + SM_AH + off) = hh;
            *reinterpret_cast<uint2*>(smem + SM_AL + off) = ll;
        }

        // ---- MODE 0: zero this tile's g_agg slice (coalesced) ----
        if (MODE == 0) {
            float4* zp = reinterpret_cast<float4*>(g_agg) + (size_t)tile * 2048;
            const float4 z = make_float4(0.f, 0.f, 0.f, 0.f);
#pragma unroll
            for (int j = 0; j < 8; j++) zp[tid + j * 256] = z;
        }
        __syncthreads();

        // ---- prefetch NEXT tile's A (in flight during MMA + epilogue) ----
        {
            const int tn = tile + gridDim.x;
            if (tn < ntiles) {
                const long long base = (long long)tn * 2048;
#pragma unroll
                for (int j = 0; j < 8; j++) {
                    long long gi = base + (tid + 256 * j);
                    av[j] = __ldg(A4 + (gi <= max4 ? gi : max4));
                    if (MODE == 1) {
                        int row = (int)(gi >> 5);
                        m8[j] = (row < N && __ldg(&mask[row < N ? row : 0]) != 0)
                                    ? 1.f : 0.f;
                    }
                }
            }
        }

        // ---- accumulators ----
        float acc[2][4][4];
#pragma unroll
        for (int mt = 0; mt < 2; mt++)
#pragma unroll
            for (int nt = 0; nt < 4; nt++) {
                acc[mt][nt][0] = acc[mt][nt][1] = acc[mt][nt][2] = acc[mt][nt][3] = 0.f;
            }

        // ---- k-loop (8 k-steps), single frag buffer; cross-warp hiding ----
#pragma unroll
        for (int ks = 0; ks < 8; ks++) {
            const uint32_t kb = (uint32_t)(ks * 32);
            LDSM_X4(fa[0], fa[1], fa[2], fa[3], ahb + kb);
            LDSM_X4(fa[4], fa[5], fa[6], fa[7], ahb + 16 * ROWB + kb);
            LDSM_X4(fa[8], fa[9], fa[10], fa[11], alb + kb);
            LDSM_X4(fa[12], fa[13], fa[14], fa[15], alb + 16 * ROWB + kb);
            LDSM_X4(fbh[0], fbh[1], fbh[2], fbh[3], whi + kb);
            LDSM_X4(fbh[4], fbh[5], fbh[6], fbh[7], whi + 16 * ROWB + kb);
            LDSM_X4(fbl[0], fbl[1], fbl[2], fbl[3], wlo + kb);
            LDSM_X4(fbl[4], fbl[5], fbl[6], fbl[7], wlo + 16 * ROWB + kb);
#pragma unroll
            for (int nt = 0; nt < 4; nt++) {
                MMA16816(acc[0][nt], fa[0], fa[1], fa[2], fa[3], fbh[2 * nt], fbh[2 * nt + 1]);
                MMA16816(acc[1][nt], fa[4], fa[5], fa[6], fa[7], fbh[2 * nt], fbh[2 * nt + 1]);
            }
#pragma unroll
            for (int nt = 0; nt < 4; nt++) {
                MMA16816(acc[0][nt], fa[8], fa[9], fa[10], fa[11], fbh[2 * nt], fbh[2 * nt + 1]);
                MMA16816(acc[1][nt], fa[12], fa[13], fa[14], fa[15], fbh[2 * nt], fbh[2 * nt + 1]);
            }
#pragma unroll
            for (int nt = 0; nt < 4; nt++) {
                MMA16816(acc[0][nt], fa[0], fa[1], fa[2], fa[3], fbl[2 * nt], fbl[2 * nt + 1]);
                MMA16816(acc[1][nt], fa[4], fa[5], fa[6], fa[7], fbl[2 * nt], fbl[2 * nt + 1]);
            }
        }

        // ---- stage acc into smem (A region is dead after the k-loop) ----
        __syncthreads();
#pragma unroll
        for (int mt = 0; mt < 2; mt++) {
            const int rA = m0 + mt * 16 + tq;
#pragma unroll
            for (int nt = 0; nt < 4; nt++) {
                const int c = n0 + nt * 8 + 2 * t4;
                *reinterpret_cast<float2*>(&epi[rA * ROWF + c]) =
                    make_float2(acc[mt][nt][0], acc[mt][nt][1]);
                *reinterpret_cast<float2*>(&epi[(rA + 8) * ROWF + c]) =
                    make_float2(acc[mt][nt][2], acc[mt][nt][3]);
            }
        }
        __syncthreads();

        // ---- linear float4 epilogue (fully coalesced global traffic) ----
#pragma unroll
        for (int j = 0; j < 8; j++) {
            int idx = tid + 256 * j;
            int row_l = idx >> 5;
            int c4 = idx & 31;
            int rg = row0 + row_l;
            if (rg >= N) continue;
            float4 v = *reinterpret_cast<const float4*>(&epi[row_l * ROWF + c4 * 4]);
            size_t g4 = (size_t)rg * 32 + c4;
            if (MODE == 0) {
                reinterpret_cast<float4*>(outp)[g4] = v;
            } else {
                float4 ag = __ldg(agg4 + g4);
                float4 bi = __ldg(bin4 + c4);
                float4 ba = __ldg(bag4 + c4);
                float m = (__ldg(&mask[rg]) != 0) ? 1.f : 0.f;
                float4 o;
                o.x = tanh_fast(v.x + ag.x + m * bi.x + ba.x);
                o.y = tanh_fast(v.y + ag.y + m * bi.y + ba.y);
                o.z = tanh_fast(v.z + ag.z + m * bi.z + ba.z);
                o.w = tanh_fast(v.w + ag.w + m * bi.w + ba.w);
                reinterpret_cast<float4*>(outp)[g4] = o;
            }
        }
    }
}

// ---------------------------------------------------------------------------
// Launch
// ---------------------------------------------------------------------------
extern "C" void kernel_launch(void* const* d_in, const int* in_sizes, int n_in,
                              void* d_out, int out_size) {
    const float* x     = (const float*)d_in[0];
    const float* h     = (const float*)d_in[1];
    const float* Win   = (const float*)d_in[2];
    const float* bin   = (const float*)d_in[3];
    const float* Waggr = (const float*)d_in[4];
    const float* baggr = (const float*)d_in[5];
    const int* mask    = (const int*)d_in[6];
    const int* esrc    = (const int*)d_in[7];
    const int* edst    = (const int*)d_in[8];
    float* out = (float*)d_out;

    const int N = in_sizes[0] / 128;
    const int E = in_sizes[7];
    const int ntiles = (N + 63) / 64;

    static int smem_set = 0;
    if (!smem_set) {
        cudaFuncSetAttribute(gemm_phase<0>, cudaFuncAttributeMaxDynamicSharedMemorySize,
                             (int)SM_TOTAL);
        cudaFuncSetAttribute(gemm_phase<1>, cudaFuncAttributeMaxDynamicSharedMemorySize,
                             (int)SM_TOTAL);
        smem_set = 1;
    }

    unsigned int* wimg_dev = nullptr;
    cudaGetSymbolAddress((void**)&wimg_dev, g_wimg);
    float* hw_dev = nullptr;
    cudaGetSymbolAddress((void**)&hw_dev, g_hw);

    prep_w<<<128, 64>>>(Win, Waggr);
    // gemm1: hW = h @ W_aggr (images 2,3); also zeroes g_agg
    gemm_phase<0><<<296, 256, SM_TOTAL>>>(h, wimg_dev + 2 * 8192, nullptr, nullptr,
                                          nullptr, hw_dev, N, ntiles);
    // scatter: g_agg[dst] += hW[src]
    scatter_kernel<<<(E + 7) / 8, 256>>>(esrc, edst, E);
    // gemm2: out = tanh(x_m @ W_in + g_agg + m*b_in + b_aggr)   (images 0,1)
    gemm_phase<1><<<296, 256, SM_TOTAL>>>(x, wimg_dev, bin, baggr, mask, out, N,
                                          ntiles);
}

// round 13
// speedup vs baseline: 1.2810x; 1.0008x over previous
#include <cuda_runtime.h>
#include <cuda_bf16.h>
#include <cstdint>
#include <cstddef>

// ---------------------------------------------------------------------------
// TreeRNNCell: out = tanh( mask*(x@W_in + b_in) + segsum(h[src]->dst)@W_aggr + b_aggr )
// N = 500000, E = 500000, X = H = 128.
//
// R12: R11 +
//   - MODE 1 epilogue: agg tile loads issued right after the k-loop into
//     (dead frag) registers, so the DRAM round trip hides under acc staging.
//   - scatter: 2 edges per warp, both loads issued before both REDs (MLP=2).
// Pipeline: prep_w -> gemm1(hW=h@W_aggr, zero agg) -> scatter(hW) -> gemm2.
// ---------------------------------------------------------------------------

#define MAXN 500000
#define NPAD 500032  // ntiles*64 rounding for fused agg-zero
__device__ float g_agg[(size_t)NPAD * 128];
__device__ float g_hw[(size_t)MAXN * 128];
// 4 images: [Win_hi, Win_lo, Wag_hi, Wag_lo], each [128n][64 uint] = bf16x2[n][k]
__device__ __align__(16) unsigned int g_wimg[4 * 8192];

__device__ __forceinline__ float tanh_fast(float x) {
    float r; asm("tanh.approx.f32 %0, %1;" : "=f"(r) : "f"(x)); return r;
}
__device__ __forceinline__ uint32_t smem_u32(const void* p) {
    uint32_t a;
    asm("{ .reg .u64 t; cvta.to.shared.u64 t, %1; cvt.u32.u64 %0, t; }" : "=r"(a) : "l"(p));
    return a;
}
__device__ __forceinline__ uint32_t pack_split(float a, float b, uint32_t& lo) {
    __nv_bfloat16 ha = __float2bfloat16(a), hb = __float2bfloat16(b);
    __nv_bfloat16 la = __float2bfloat16(a - __bfloat162float(ha));
    __nv_bfloat16 lb = __float2bfloat16(b - __bfloat162float(hb));
    lo = ((uint32_t)__bfloat16_as_ushort(lb) << 16) | __bfloat16_as_ushort(la);
    return ((uint32_t)__bfloat16_as_ushort(hb) << 16) | __bfloat16_as_ushort(ha);
}

#define LDSM_X4(r0, r1, r2, r3, addr) \
    asm volatile("ldmatrix.sync.aligned.m8n8.x4.shared.b16 {%0,%1,%2,%3}, [%4];" \
                 : "=r"(r0), "=r"(r1), "=r"(r2), "=r"(r3) : "r"(addr))

#define MMA16816(acc, a0, a1, a2, a3, b0, b1) \
    asm volatile("mma.sync.aligned.m16n8k16.row.col.f32.bf16.bf16.f32 " \
                 "{%0,%1,%2,%3}, {%4,%5,%6,%7}, {%8,%9}, {%0,%1,%2,%3};" \
                 : "+f"((acc)[0]), "+f"((acc)[1]), "+f"((acc)[2]), "+f"((acc)[3]) \
                 : "r"(a0), "r"(a1), "r"(a2), "r"(a3), "r"(b0), "r"(b1))

// smem layout: rows padded to 136 bf16 (272 B) -> conflict-free ldmatrix.
#define ROWB 272u
#define ROWF 132                     // epilogue f32 stage row stride (528 B)
#define WIMGB (128u * ROWB)          // 34816 per W image
#define AIMGB (64u * ROWB)           // 17408 per A image
#define SM_WH 0u
#define SM_WL WIMGB                  // 34816
#define SM_AH (2u * WIMGB)           // 69632
#define SM_AL (SM_AH + AIMGB)        // 87040
#define SM_TOTAL (SM_AL + AIMGB)     // 104448 (102 KB) -> 2 CTAs/SM
// epilogue stage overlays SM_AH..: 64*132*4 = 33792 <= 2*AIMGB = 34816  OK

// ---------------------------------------------------------------------------
// Kernel 0: build bf16 hi/lo W images (plain [n][k-pair] layout)
// ---------------------------------------------------------------------------
__global__ void prep_w(const float* __restrict__ Win, const float* __restrict__ Wag) {
    int n = blockIdx.x;     // output feature 0..127
    int kp = threadIdx.x;   // k-pair 0..63
    int k0 = kp * 2;
    float a0 = Win[k0 * 128 + n], a1 = Win[(k0 + 1) * 128 + n];
    float b0 = Wag[k0 * 128 + n], b1 = Wag[(k0 + 1) * 128 + n];
    uint32_t alo, blo;
    uint32_t ahi = pack_split(a0, a1, alo);
    uint32_t bhi = pack_split(b0, b1, blo);
    int idx = n * 64 + kp;
    g_wimg[0 * 8192 + idx] = ahi;
    g_wimg[1 * 8192 + idx] = alo;
    g_wimg[2 * 8192 + idx] = bhi;
    g_wimg[3 * 8192 + idx] = blo;
}

// ---------------------------------------------------------------------------
// Kernel 2: scatter-add  g_agg[dst] += g_hw[src]  (2 edges per warp, MLP=2)
// ---------------------------------------------------------------------------
__global__ void scatter_kernel(const int* __restrict__ src,
                               const int* __restrict__ dst, int E) {
    int warp = (blockIdx.x * blockDim.x + threadIdx.x) >> 5;
    int lane = threadIdx.x & 31;
    int e0 = warp * 2;
    int e1 = e0 + 1;
    if (e0 >= E) return;
    int s0 = __ldg(&src[e0]);
    int d0 = __ldg(&dst[e0]);
    const float4 v0 = __ldg(reinterpret_cast<const float4*>(g_hw + (size_t)s0 * 128) + lane);
    bool has1 = (e1 < E);
    int s1 = has1 ? __ldg(&src[e1]) : 0;
    int d1 = has1 ? __ldg(&dst[e1]) : 0;
    float4 v1 = __ldg(reinterpret_cast<const float4*>(g_hw + (size_t)s1 * 128) + lane);
    float* p0 = g_agg + (size_t)d0 * 128 + lane * 4;
    asm volatile("red.global.add.v4.f32 [%0], {%1,%2,%3,%4};"
                 :: "l"(p0), "f"(v0.x), "f"(v0.y), "f"(v0.z), "f"(v0.w) : "memory");
    if (has1) {
        float* p1 = g_agg + (size_t)d1 * 128 + lane * 4;
        asm volatile("red.global.add.v4.f32 [%0], {%1,%2,%3,%4};"
                     :: "l"(p1), "f"(v1.x), "f"(v1.y), "f"(v1.z), "f"(v1.w) : "memory");
    }
}

// ---------------------------------------------------------------------------
// GEMM (persistent): CTA = 64 rows x 128 cols; warp tile 32x32 (grid 2x4).
// MODE 0: outp = A @ W, and zero g_agg slice    (gemm1: A=h, W=W_aggr pair)
// MODE 1: outp = tanh(A_m @ W + g_agg + m*bin + baggr)  (gemm2: A=x, W=W_in)
// Epilogue: agg LDGs issued pre-staging (hidden); acc -> smem stage ->
// linear float4 global.
// ---------------------------------------------------------------------------
template <int MODE>
__global__ void __launch_bounds__(256, 2) gemm_phase(
    const float* __restrict__ A, const unsigned int* __restrict__ wpair,
    const float* __restrict__ bin, const float* __restrict__ baggr,
    const int* __restrict__ mask, float* __restrict__ outp, int N, int ntiles) {
    extern __shared__ char smem[];
    const uint32_t sbase = smem_u32(smem);
    float* epi = reinterpret_cast<float*>(smem + SM_AH);  // post-k-loop overlay
    const int tid = threadIdx.x;
    const int wid = tid >> 5;
    const int lid = tid & 31;

    const float4* A4 = reinterpret_cast<const float4*>(A);
    const float4* agg4 = reinterpret_cast<const float4*>(g_agg);
    const float4* bin4 = reinterpret_cast<const float4*>(bin);
    const float4* bag4 = reinterpret_cast<const float4*>(baggr);
    const long long max4 = (long long)N * 32 - 1;  // last valid float4 index

    // ---- prefetch A tile for first assigned tile (coalesced linear map) ----
    float4 av[8];
    float m8[8];
    {
        const long long base = (long long)blockIdx.x * 2048;
#pragma unroll
        for (int j = 0; j < 8; j++) {
            long long gi = base + (tid + 256 * j);
            av[j] = __ldg(A4 + (gi <= max4 ? gi : max4));
            if (MODE == 1) {
                int row = (int)(gi >> 5);
                m8[j] = (row < N && __ldg(&mask[row < N ? row : 0]) != 0) ? 1.f : 0.f;
            }
        }
    }

    // ---- copy W hi/lo pair into smem ONCE (persistent CTA) ----
    {
        const uint4* src = reinterpret_cast<const uint4*>(wpair);
#pragma unroll
        for (int it = 0; it < 16; it++) {
            int idx = tid + it * 256;        // 4096 uint4 (2 images)
            int row = idx >> 4;              // 0..255: img*128 + n
            int j = idx & 15;
            int img = row >> 7, n = row & 127;
            *reinterpret_cast<uint4*>(smem + SM_WH + (uint32_t)img * WIMGB +
                                      (uint32_t)n * ROWB + (uint32_t)j * 16) = src[idx];
        }
    }

    // warp tile: rows m0..m0+31, cols n0..n0+31
    const int wr = wid >> 2;       // 0..1
    const int wc = wid & 3;        // 0..3
    const int m0 = wr * 32;
    const int n0 = wc * 32;

    const int l8 = lid & 7;
    const int quad = lid >> 3;
    const uint32_t a_lane_off =
        (uint32_t)((m0 + l8 + (quad & 1) * 8) * ROWB + ((quad >> 1) * 8) * 2);
    const uint32_t b_lane_off =
        (uint32_t)((n0 + l8 + (quad >> 1) * 8) * ROWB + ((quad & 1) * 8) * 2);
    const uint32_t whi = sbase + SM_WH + b_lane_off;
    const uint32_t wlo = sbase + SM_WL + b_lane_off;
    const uint32_t ahb = sbase + SM_AH + a_lane_off;
    const uint32_t alb = sbase + SM_AL + a_lane_off;

    // acc->stage mapping
    const int tq = lid >> 2;   // 0..7
    const int t4 = lid & 3;    // 0..3

    for (int tile = blockIdx.x; tile < ntiles; tile += gridDim.x) {
        const int row0 = tile * 64;

        __syncthreads();  // epilogue stage reads done; W copy ordered (tile 0)

        // ---- convert + store A tile from prefetched regs (mask folded) ----
#pragma unroll
        for (int j = 0; j < 8; j++) {
            int idx = tid + 256 * j;
            int row_l = idx >> 5;
            int c4 = idx & 31;
            float4 v = av[j];
            if (MODE == 1) { v.x *= m8[j]; v.y *= m8[j]; v.z *= m8[j]; v.w *= m8[j]; }
            uint32_t lo01, lo23;
            uint32_t hi01 = pack_split(v.x, v.y, lo01);
            uint32_t hi23 = pack_split(v.z, v.w, lo23);
            uint32_t off = (uint32_t)(row_l * ROWB + c4 * 8);
            uint2 hh; hh.x = hi01; hh.y = hi23;
            uint2 ll; ll.x = lo01; ll.y = lo23;
            *reinterpret_cast<uint2*>(smem + SM_AH + off) = hh;
            *reinterpret_cast<uint2*>(smem + SM_AL + off) = ll;
        }

        // ---- MODE 0: zero this tile's g_agg slice (coalesced) ----
        if (MODE == 0) {
            float4* zp = reinterpret_cast<float4*>(g_agg) + (size_t)tile * 2048;
            const float4 z = make_float4(0.f, 0.f, 0.f, 0.f);
#pragma unroll
            for (int j = 0; j < 8; j++) zp[tid + j * 256] = z;
        }
        __syncthreads();

        // ---- prefetch NEXT tile's A (in flight during MMA + epilogue) ----
        {
            const int tn = tile + gridDim.x;
            if (tn < ntiles) {
                const long long base = (long long)tn * 2048;
#pragma unroll
                for (int j = 0; j < 8; j++) {
                    long long gi = base + (tid + 256 * j);
                    av[j] = __ldg(A4 + (gi <= max4 ? gi : max4));
                    if (MODE == 1) {
                        int row = (int)(gi >> 5);
                        m8[j] = (row < N && __ldg(&mask[row < N ? row : 0]) != 0)
                                    ? 1.f : 0.f;
                    }
                }
            }
        }

        // ---- accumulators ----
        float acc[2][4][4];
#pragma unroll
        for (int mt = 0; mt < 2; mt++)
#pragma unroll
            for (int nt = 0; nt < 4; nt++) {
                acc[mt][nt][0] = acc[mt][nt][1] = acc[mt][nt][2] = acc[mt][nt][3] = 0.f;
            }

        // ---- k-loop (8 k-steps), single frag buffer; cross-warp hiding ----
        {
            uint32_t fa[16], fbh[8], fbl[8];
#pragma unroll
            for (int ks = 0; ks < 8; ks++) {
                const uint32_t kb = (uint32_t)(ks * 32);
                LDSM_X4(fa[0], fa[1], fa[2], fa[3], ahb + kb);
                LDSM_X4(fa[4], fa[5], fa[6], fa[7], ahb + 16 * ROWB + kb);
                LDSM_X4(fa[8], fa[9], fa[10], fa[11], alb + kb);
                LDSM_X4(fa[12], fa[13], fa[14], fa[15], alb + 16 * ROWB + kb);
                LDSM_X4(fbh[0], fbh[1], fbh[2], fbh[3], whi + kb);
                LDSM_X4(fbh[4], fbh[5], fbh[6], fbh[7], whi + 16 * ROWB + kb);
                LDSM_X4(fbl[0], fbl[1], fbl[2], fbl[3], wlo + kb);
                LDSM_X4(fbl[4], fbl[5], fbl[6], fbl[7], wlo + 16 * ROWB + kb);
#pragma unroll
                for (int nt = 0; nt < 4; nt++) {
                    MMA16816(acc[0][nt], fa[0], fa[1], fa[2], fa[3], fbh[2 * nt], fbh[2 * nt + 1]);
                    MMA16816(acc[1][nt], fa[4], fa[5], fa[6], fa[7], fbh[2 * nt], fbh[2 * nt + 1]);
                }
#pragma unroll
                for (int nt = 0; nt < 4; nt++) {
                    MMA16816(acc[0][nt], fa[8], fa[9], fa[10], fa[11], fbh[2 * nt], fbh[2 * nt + 1]);
                    MMA16816(acc[1][nt], fa[12], fa[13], fa[14], fa[15], fbh[2 * nt], fbh[2 * nt + 1]);
                }
#pragma unroll
                for (int nt = 0; nt < 4; nt++) {
                    MMA16816(acc[0][nt], fa[0], fa[1], fa[2], fa[3], fbl[2 * nt], fbl[2 * nt + 1]);
                    MMA16816(acc[1][nt], fa[4], fa[5], fa[6], fa[7], fbl[2 * nt], fbl[2 * nt + 1]);
                }
            }
        }

        // ---- MODE 1: issue agg loads NOW (hidden under staging) ----
        float4 ag[8];
        if (MODE == 1) {
#pragma unroll
            for (int j = 0; j < 8; j++) {
                long long gi = (long long)tile * 2048 + (tid + 256 * j);
                ag[j] = __ldg(agg4 + (gi <= max4 ? gi : max4));
            }
        }

        // ---- stage acc into smem (A region is dead after the k-loop) ----
        __syncthreads();
#pragma unroll
        for (int mt = 0; mt < 2; mt++) {
            const int rA = m0 + mt * 16 + tq;
#pragma unroll
            for (int nt = 0; nt < 4; nt++) {
                const int c = n0 + nt * 8 + 2 * t4;
                *reinterpret_cast<float2*>(&epi[rA * ROWF + c]) =
                    make_float2(acc[mt][nt][0], acc[mt][nt][1]);
                *reinterpret_cast<float2*>(&epi[(rA + 8) * ROWF + c]) =
                    make_float2(acc[mt][nt][2], acc[mt][nt][3]);
            }
        }
        __syncthreads();

        // ---- linear float4 epilogue (fully coalesced global traffic) ----
#pragma unroll
        for (int j = 0; j < 8; j++) {
            int idx = tid + 256 * j;
            int row_l = idx >> 5;
            int c4 = idx & 31;
            int rg = row0 + row_l;
            if (rg >= N) continue;
            float4 v = *reinterpret_cast<const float4*>(&epi[row_l * ROWF + c4 * 4]);
            size_t g4 = (size_t)rg * 32 + c4;
            if (MODE == 0) {
                reinterpret_cast<float4*>(outp)[g4] = v;
            } else {
                float4 bi = __ldg(bin4 + c4);
                float4 ba = __ldg(bag4 + c4);
                float m = m8[0], mm;  // dummy init; real mask below
                mm = (__ldg(&mask[rg]) != 0) ? 1.f : 0.f;
                (void)m;
                float4 o;
                o.x = tanh_fast(v.x + ag[j].x + mm * bi.x + ba.x);
                o.y = tanh_fast(v.y + ag[j].y + mm * bi.y + ba.y);
                o.z = tanh_fast(v.z + ag[j].z + mm * bi.z + ba.z);
                o.w = tanh_fast(v.w + ag[j].w + mm * bi.w + ba.w);
                reinterpret_cast<float4*>(outp)[g4] = o;
            }
        }
    }
}

// ---------------------------------------------------------------------------
// Launch
// ---------------------------------------------------------------------------
extern "C" void kernel_launch(void* const* d_in, const int* in_sizes, int n_in,
                              void* d_out, int out_size) {
    const float* x     = (const float*)d_in[0];
    const float* h     = (const float*)d_in[1];
    const float* Win   = (const float*)d_in[2];
    const float* bin   = (const float*)d_in[3];
    const float* Waggr = (const float*)d_in[4];
    const float* baggr = (const float*)d_in[5];
    const int* mask    = (const int*)d_in[6];
    const int* esrc    = (const int*)d_in[7];
    const int* edst    = (const int*)d_in[8];
    float* out = (float*)d_out;

    const int N = in_sizes[0] / 128;
    const int E = in_sizes[7];
    const int ntiles = (N + 63) / 64;

    static int smem_set = 0;
    if (!smem_set) {
        cudaFuncSetAttribute(gemm_phase<0>, cudaFuncAttributeMaxDynamicSharedMemorySize,
                             (int)SM_TOTAL);
        cudaFuncSetAttribute(gemm_phase<1>, cudaFuncAttributeMaxDynamicSharedMemorySize,
                             (int)SM_TOTAL);
        smem_set = 1;
    }

    unsigned int* wimg_dev = nullptr;
    cudaGetSymbolAddress((void**)&wimg_dev, g_wimg);
    float* hw_dev = nullptr;
    cudaGetSymbolAddress((void**)&hw_dev, g_hw);

    prep_w<<<128, 64>>>(Win, Waggr);
    // gemm1: hW = h @ W_aggr (images 2,3); also zeroes g_agg
    gemm_phase<0><<<296, 256, SM_TOTAL>>>(h, wimg_dev + 2 * 8192, nullptr, nullptr,
                                          nullptr, hw_dev, N, ntiles);
    // scatter: g_agg[dst] += hW[src]
    const int warps_needed = (E + 1) / 2;
    scatter_kernel<<<(warps_needed + 7) / 8, 256>>>(esrc, edst, E);
    // gemm2: out = tanh(x_m @ W_in + g_agg + m*b_in + b_aggr)   (images 0,1)
    gemm_phase<1><<<296, 256, SM_TOTAL>>>(x, wimg_dev, bin, baggr, mask, out, N,
                                          ntiles);
}

// round 14
// speedup vs baseline: 1.3206x; 1.0309x over previous
#include <cuda_runtime.h>
#include <cuda_bf16.h>
#include <cstdint>
#include <cstddef>

// ---------------------------------------------------------------------------
// TreeRNNCell: out = tanh( mask*(x@W_in + b_in) + segsum(h[src]->dst)@W_aggr + b_aggr )
// N = 500000, E = 500000, X = H = 128.
//
// R13: R12 + per-tile fixed-cost shaving:
//   - bias vectors hoisted to registers (epilogue c4 is constant per thread)
//   - fp32->bf16 hi/lo split via cvt.rn.bf16x2.f32 (pairwise, fewer ALU ops)
//   - scatter: 4 edges/warp, loads batched ahead of REDs (MLP=4)
// Pipeline: prep_w -> gemm1(hW=h@W_aggr, zero agg) -> scatter(hW) -> gemm2.
// ---------------------------------------------------------------------------

#define MAXN 500000
#define NPAD 500032  // ntiles*64 rounding for fused agg-zero
__device__ float g_agg[(size_t)NPAD * 128];
__device__ float g_hw[(size_t)MAXN * 128];
// 4 images: [Win_hi, Win_lo, Wag_hi, Wag_lo], each [128n][64 uint] = bf16x2[n][k]
__device__ __align__(16) unsigned int g_wimg[4 * 8192];

__device__ __forceinline__ float tanh_fast(float x) {
    float r; asm("tanh.approx.f32 %0, %1;" : "=f"(r) : "f"(x)); return r;
}
__device__ __forceinline__ uint32_t smem_u32(const void* p) {
    uint32_t a;
    asm("{ .reg .u64 t; cvta.to.shared.u64 t, %1; cvt.u32.u64 %0, t; }" : "=r"(a) : "l"(p));
    return a;
}
// Pairwise split: hi = bf16x2(a,b); lo = bf16x2(a-hi.a, b-hi.b). Uses packed cvt.
__device__ __forceinline__ void pack2_split(float a, float b, uint32_t& hi, uint32_t& lo) {
    asm("cvt.rn.bf16x2.f32 %0, %1, %2;" : "=r"(hi) : "f"(b), "f"(a));
    float ha = __uint_as_float(hi << 16);
    float hb = __uint_as_float(hi & 0xFFFF0000u);
    float ra = a - ha, rb = b - hb;
    asm("cvt.rn.bf16x2.f32 %0, %1, %2;" : "=r"(lo) : "f"(rb), "f"(ra));
}
// scalar variant for prep_w (keeps layout identical)
__device__ __forceinline__ uint32_t pack_split(float a, float b, uint32_t& lo) {
    uint32_t hi;
    pack2_split(a, b, hi, lo);
    return hi;
}

#define LDSM_X4(r0, r1, r2, r3, addr) \
    asm volatile("ldmatrix.sync.aligned.m8n8.x4.shared.b16 {%0,%1,%2,%3}, [%4];" \
                 : "=r"(r0), "=r"(r1), "=r"(r2), "=r"(r3) : "r"(addr))

#define MMA16816(acc, a0, a1, a2, a3, b0, b1) \
    asm volatile("mma.sync.aligned.m16n8k16.row.col.f32.bf16.bf16.f32 " \
                 "{%0,%1,%2,%3}, {%4,%5,%6,%7}, {%8,%9}, {%0,%1,%2,%3};" \
                 : "+f"((acc)[0]), "+f"((acc)[1]), "+f"((acc)[2]), "+f"((acc)[3]) \
                 : "r"(a0), "r"(a1), "r"(a2), "r"(a3), "r"(b0), "r"(b1))

// smem layout: rows padded to 136 bf16 (272 B) -> conflict-free ldmatrix.
#define ROWB 272u
#define ROWF 132                     // epilogue f32 stage row stride (528 B)
#define WIMGB (128u * ROWB)          // 34816 per W image
#define AIMGB (64u * ROWB)           // 17408 per A image
#define SM_WH 0u
#define SM_WL WIMGB                  // 34816
#define SM_AH (2u * WIMGB)           // 69632
#define SM_AL (SM_AH + AIMGB)        // 87040
#define SM_TOTAL (SM_AL + AIMGB)     // 104448 (102 KB) -> 2 CTAs/SM
// epilogue stage overlays SM_AH..: 64*132*4 = 33792 <= 2*AIMGB = 34816  OK

// ---------------------------------------------------------------------------
// Kernel 0: build bf16 hi/lo W images (plain [n][k-pair] layout)
// ---------------------------------------------------------------------------
__global__ void prep_w(const float* __restrict__ Win, const float* __restrict__ Wag) {
    int n = blockIdx.x;     // output feature 0..127
    int kp = threadIdx.x;   // k-pair 0..63
    int k0 = kp * 2;
    float a0 = Win[k0 * 128 + n], a1 = Win[(k0 + 1) * 128 + n];
    float b0 = Wag[k0 * 128 + n], b1 = Wag[(k0 + 1) * 128 + n];
    uint32_t alo, blo;
    uint32_t ahi = pack_split(a0, a1, alo);
    uint32_t bhi = pack_split(b0, b1, blo);
    int idx = n * 64 + kp;
    g_wimg[0 * 8192 + idx] = ahi;
    g_wimg[1 * 8192 + idx] = alo;
    g_wimg[2 * 8192 + idx] = bhi;
    g_wimg[3 * 8192 + idx] = blo;
}

// ---------------------------------------------------------------------------
// Kernel 2: scatter-add  g_agg[dst] += g_hw[src]  (4 edges per warp, MLP=4)
// ---------------------------------------------------------------------------
__global__ void scatter_kernel(const int* __restrict__ src,
                               const int* __restrict__ dst, int E) {
    int warp = (blockIdx.x * blockDim.x + threadIdx.x) >> 5;
    int lane = threadIdx.x & 31;
    int e0 = warp * 4;
    if (e0 >= E) return;
    int s[4], d[4];
    float4 v[4];
    int cnt = (E - e0 < 4) ? (E - e0) : 4;
#pragma unroll
    for (int i = 0; i < 4; i++) {
        int e = (i < cnt) ? e0 + i : e0;
        s[i] = __ldg(&src[e]);
        d[i] = __ldg(&dst[e]);
    }
#pragma unroll
    for (int i = 0; i < 4; i++)
        v[i] = __ldg(reinterpret_cast<const float4*>(g_hw + (size_t)s[i] * 128) + lane);
#pragma unroll
    for (int i = 0; i < 4; i++) {
        if (i < cnt) {
            float* p = g_agg + (size_t)d[i] * 128 + lane * 4;
            asm volatile("red.global.add.v4.f32 [%0], {%1,%2,%3,%4};"
                         :: "l"(p), "f"(v[i].x), "f"(v[i].y), "f"(v[i].z), "f"(v[i].w)
                         : "memory");
        }
    }
}

// ---------------------------------------------------------------------------
// GEMM (persistent): CTA = 64 rows x 128 cols; warp tile 32x32 (grid 2x4).
// MODE 0: outp = A @ W, and zero g_agg slice    (gemm1: A=h, W=W_aggr pair)
// MODE 1: outp = tanh(A_m @ W + g_agg + m*bin + baggr)  (gemm2: A=x, W=W_in)
// ---------------------------------------------------------------------------
template <int MODE>
__global__ void __launch_bounds__(256, 2) gemm_phase(
    const float* __restrict__ A, const unsigned int* __restrict__ wpair,
    const float* __restrict__ bin, const float* __restrict__ baggr,
    const int* __restrict__ mask, float* __restrict__ outp, int N, int ntiles) {
    extern __shared__ char smem[];
    const uint32_t sbase = smem_u32(smem);
    float* epi = reinterpret_cast<float*>(smem + SM_AH);  // post-k-loop overlay
    const int tid = threadIdx.x;
    const int wid = tid >> 5;
    const int lid = tid & 31;

    const float4* A4 = reinterpret_cast<const float4*>(A);
    const float4* agg4 = reinterpret_cast<const float4*>(g_agg);
    const long long max4 = (long long)N * 32 - 1;  // last valid float4 index

    // ---- hoisted bias registers (epilogue column block = tid&31, constant) ----
    float4 bi_r = make_float4(0.f, 0.f, 0.f, 0.f);
    float4 ba_r = make_float4(0.f, 0.f, 0.f, 0.f);
    if (MODE == 1) {
        bi_r = __ldg(reinterpret_cast<const float4*>(bin) + (tid & 31));
        ba_r = __ldg(reinterpret_cast<const float4*>(baggr) + (tid & 31));
    }

    // ---- prefetch A tile for first assigned tile (coalesced linear map) ----
    float4 av[8];
    float m8[8];
    {
        const long long base = (long long)blockIdx.x * 2048;
#pragma unroll
        for (int j = 0; j < 8; j++) {
            long long gi = base + (tid + 256 * j);
            av[j] = __ldg(A4 + (gi <= max4 ? gi : max4));
            if (MODE == 1) {
                int row = (int)(gi >> 5);
                m8[j] = (row < N && __ldg(&mask[row < N ? row : 0]) != 0) ? 1.f : 0.f;
            }
        }
    }

    // ---- copy W hi/lo pair into smem ONCE (persistent CTA) ----
    {
        const uint4* src = reinterpret_cast<const uint4*>(wpair);
#pragma unroll
        for (int it = 0; it < 16; it++) {
            int idx = tid + it * 256;        // 4096 uint4 (2 images)
            int row = idx >> 4;              // 0..255: img*128 + n
            int j = idx & 15;
            int img = row >> 7, n = row & 127;
            *reinterpret_cast<uint4*>(smem + SM_WH + (uint32_t)img * WIMGB +
                                      (uint32_t)n * ROWB + (uint32_t)j * 16) = src[idx];
        }
    }

    // warp tile: rows m0..m0+31, cols n0..n0+31
    const int wr = wid >> 2;       // 0..1
    const int wc = wid & 3;        // 0..3
    const int m0 = wr * 32;
    const int n0 = wc * 32;

    const int l8 = lid & 7;
    const int quad = lid >> 3;
    const uint32_t a_lane_off =
        (uint32_t)((m0 + l8 + (quad & 1) * 8) * ROWB + ((quad >> 1) * 8) * 2);
    const uint32_t b_lane_off =
        (uint32_t)((n0 + l8 + (quad >> 1) * 8) * ROWB + ((quad & 1) * 8) * 2);
    const uint32_t whi = sbase + SM_WH + b_lane_off;
    const uint32_t wlo = sbase + SM_WL + b_lane_off;
    const uint32_t ahb = sbase + SM_AH + a_lane_off;
    const uint32_t alb = sbase + SM_AL + a_lane_off;

    // acc->stage mapping
    const int tq = lid >> 2;   // 0..7
    const int t4 = lid & 3;    // 0..3

    for (int tile = blockIdx.x; tile < ntiles; tile += gridDim.x) {
        const int row0 = tile * 64;

        __syncthreads();  // epilogue stage reads done; W copy ordered (tile 0)

        // ---- convert + store A tile from prefetched regs (mask folded) ----
#pragma unroll
        for (int j = 0; j < 8; j++) {
            int idx = tid + 256 * j;
            int row_l = idx >> 5;
            int c4 = idx & 31;
            float4 v = av[j];
            if (MODE == 1) { v.x *= m8[j]; v.y *= m8[j]; v.z *= m8[j]; v.w *= m8[j]; }
            uint32_t hi01, lo01, hi23, lo23;
            pack2_split(v.x, v.y, hi01, lo01);
            pack2_split(v.z, v.w, hi23, lo23);
            uint32_t off = (uint32_t)(row_l * ROWB + c4 * 8);
            uint2 hh; hh.x = hi01; hh.y = hi23;
            uint2 ll; ll.x = lo01; ll.y = lo23;
            *reinterpret_cast<uint2*>(smem + SM_AH + off) = hh;
            *reinterpret_cast<uint2*>(smem + SM_AL + off) = ll;
        }

        // ---- MODE 0: zero this tile's g_agg slice (coalesced) ----
        if (MODE == 0) {
            float4* zp = reinterpret_cast<float4*>(g_agg) + (size_t)tile * 2048;
            const float4 z = make_float4(0.f, 0.f, 0.f, 0.f);
#pragma unroll
            for (int j = 0; j < 8; j++) zp[tid + j * 256] = z;
        }
        __syncthreads();

        // ---- prefetch NEXT tile's A (in flight during MMA + epilogue) ----
        {
            const int tn = tile + gridDim.x;
            if (tn < ntiles) {
                const long long base = (long long)tn * 2048;
#pragma unroll
                for (int j = 0; j < 8; j++) {
                    long long gi = base + (tid + 256 * j);
                    av[j] = __ldg(A4 + (gi <= max4 ? gi : max4));
                    if (MODE == 1) {
                        int row = (int)(gi >> 5);
                        m8[j] = (row < N && __ldg(&mask[row < N ? row : 0]) != 0)
                                    ? 1.f : 0.f;
                    }
                }
            }
        }

        // ---- accumulators ----
        float acc[2][4][4];
#pragma unroll
        for (int mt = 0; mt < 2; mt++)
#pragma unroll
            for (int nt = 0; nt < 4; nt++) {
                acc[mt][nt][0] = acc[mt][nt][1] = acc[mt][nt][2] = acc[mt][nt][3] = 0.f;
            }

        // ---- k-loop (8 k-steps), single frag buffer; cross-warp hiding ----
        {
            uint32_t fa[16], fbh[8], fbl[8];
#pragma unroll
            for (int ks = 0; ks < 8; ks++) {
                const uint32_t kb = (uint32_t)(ks * 32);
                LDSM_X4(fa[0], fa[1], fa[2], fa[3], ahb + kb);
                LDSM_X4(fa[4], fa[5], fa[6], fa[7], ahb + 16 * ROWB + kb);
                LDSM_X4(fa[8], fa[9], fa[10], fa[11], alb + kb);
                LDSM_X4(fa[12], fa[13], fa[14], fa[15], alb + 16 * ROWB + kb);
                LDSM_X4(fbh[0], fbh[1], fbh[2], fbh[3], whi + kb);
                LDSM_X4(fbh[4], fbh[5], fbh[6], fbh[7], whi + 16 * ROWB + kb);
                LDSM_X4(fbl[0], fbl[1], fbl[2], fbl[3], wlo + kb);
                LDSM_X4(fbl[4], fbl[5], fbl[6], fbl[7], wlo + 16 * ROWB + kb);
#pragma unroll
                for (int nt = 0; nt < 4; nt++) {
                    MMA16816(acc[0][nt], fa[0], fa[1], fa[2], fa[3], fbh[2 * nt], fbh[2 * nt + 1]);
                    MMA16816(acc[1][nt], fa[4], fa[5], fa[6], fa[7], fbh[2 * nt], fbh[2 * nt + 1]);
                }
#pragma unroll
                for (int nt = 0; nt < 4; nt++) {
                    MMA16816(acc[0][nt], fa[8], fa[9], fa[10], fa[11], fbh[2 * nt], fbh[2 * nt + 1]);
                    MMA16816(acc[1][nt], fa[12], fa[13], fa[14], fa[15], fbh[2 * nt], fbh[2 * nt + 1]);
                }
#pragma unroll
                for (int nt = 0; nt < 4; nt++) {
                    MMA16816(acc[0][nt], fa[0], fa[1], fa[2], fa[3], fbl[2 * nt], fbl[2 * nt + 1]);
                    MMA16816(acc[1][nt], fa[4], fa[5], fa[6], fa[7], fbl[2 * nt], fbl[2 * nt + 1]);
                }
            }
        }

        // ---- MODE 1: issue agg loads before staging (hidden under STS/sync) ----
        float4 ag[8];
        if (MODE == 1) {
#pragma unroll
            for (int j = 0; j < 8; j++) {
                long long gi = (long long)tile * 2048 + (tid + 256 * j);
                ag[j] = __ldg(agg4 + (gi <= max4 ? gi : max4));
            }
        }

        // ---- stage acc into smem (A region is dead after the k-loop) ----
        __syncthreads();
#pragma unroll
        for (int mt = 0; mt < 2; mt++) {
            const int rA = m0 + mt * 16 + tq;
#pragma unroll
            for (int nt = 0; nt < 4; nt++) {
                const int c = n0 + nt * 8 + 2 * t4;
                *reinterpret_cast<float2*>(&epi[rA * ROWF + c]) =
                    make_float2(acc[mt][nt][0], acc[mt][nt][1]);
                *reinterpret_cast<float2*>(&epi[(rA + 8) * ROWF + c]) =
                    make_float2(acc[mt][nt][2], acc[mt][nt][3]);
            }
        }
        __syncthreads();

        // ---- linear float4 epilogue (fully coalesced global traffic) ----
#pragma unroll
        for (int j = 0; j < 8; j++) {
            int idx = tid + 256 * j;
            int row_l = idx >> 5;
            int c4 = idx & 31;
            int rg = row0 + row_l;
            if (rg >= N) continue;
            float4 v = *reinterpret_cast<const float4*>(&epi[row_l * ROWF + c4 * 4]);
            size_t g4 = (size_t)rg * 32 + c4;
            if (MODE == 0) {
                reinterpret_cast<float4*>(outp)[g4] = v;
            } else {
                float mm = (__ldg(&mask[rg]) != 0) ? 1.f : 0.f;
                float4 o;
                o.x = tanh_fast(v.x + ag[j].x + mm * bi_r.x + ba_r.x);
                o.y = tanh_fast(v.y + ag[j].y + mm * bi_r.y + ba_r.y);
                o.z = tanh_fast(v.z + ag[j].z + mm * bi_r.z + ba_r.z);
                o.w = tanh_fast(v.w + ag[j].w + mm * bi_r.w + ba_r.w);
                reinterpret_cast<float4*>(outp)[g4] = o;
            }
        }
    }
}

// ---------------------------------------------------------------------------
// Launch
// ---------------------------------------------------------------------------
extern "C" void kernel_launch(void* const* d_in, const int* in_sizes, int n_in,
                              void* d_out, int out_size) {
    const float* x     = (const float*)d_in[0];
    const float* h     = (const float*)d_in[1];
    const float* Win   = (const float*)d_in[2];
    const float* bin   = (const float*)d_in[3];
    const float* Waggr = (const float*)d_in[4];
    const float* baggr = (const float*)d_in[5];
    const int* mask    = (const int*)d_in[6];
    const int* esrc    = (const int*)d_in[7];
    const int* edst    = (const int*)d_in[8];
    float* out = (float*)d_out;

    const int N = in_sizes[0] / 128;
    const int E = in_sizes[7];
    const int ntiles = (N + 63) / 64;

    static int smem_set = 0;
    if (!smem_set) {
        cudaFuncSetAttribute(gemm_phase<0>, cudaFuncAttributeMaxDynamicSharedMemorySize,
                             (int)SM_TOTAL);
        cudaFuncSetAttribute(gemm_phase<1>, cudaFuncAttributeMaxDynamicSharedMemorySize,
                             (int)SM_TOTAL);
        smem_set = 1;
    }

    unsigned int* wimg_dev = nullptr;
    cudaGetSymbolAddress((void**)&wimg_dev, g_wimg);
    float* hw_dev = nullptr;
    cudaGetSymbolAddress((void**)&hw_dev, g_hw);

    prep_w<<<128, 64>>>(Win, Waggr);
    // gemm1: hW = h @ W_aggr (images 2,3); also zeroes g_agg
    gemm_phase<0><<<296, 256, SM_TOTAL>>>(h, wimg_dev + 2 * 8192, nullptr, nullptr,
                                          nullptr, hw_dev, N, ntiles);
    // scatter: g_agg[dst] += hW[src]
    const int warps_needed = (E + 3) / 4;
    scatter_kernel<<<(warps_needed + 7) / 8, 256>>>(esrc, edst, E);
    // gemm2: out = tanh(x_m @ W_in + g_agg + m*b_in + b_aggr)   (images 0,1)
    gemm_phase<1><<<296, 256, SM_TOTAL>>>(x, wimg_dev, bin, baggr, mask, out, N,
                                          ntiles);
}

// round 15
// speedup vs baseline: 1.4296x; 1.0825x over previous
#include <cuda_runtime.h>
#include <cuda_fp16.h>
#include <cstdint>
#include <cstddef>

// ---------------------------------------------------------------------------
// TreeRNNCell: out = tanh( mask*(x@W_in + b_in) + segsum(h[src]->dst)@W_aggr + b_aggr )
// N = 500000, E = 500000, X = H = 128.
//
// R14: fp16 two-term split (was bf16 three-term):
//   a*w ~= ah*wh + ah*wl   (drop al*wh ~ 2^-12 rel; fp16 keeps 11 mantissa bits)
//   -> MMAs/k-step 24->16, LDSM 8->6, A needs only a hi image (smem/convert halve).
// Pipeline: prep_w -> gemm1(hW=h@W_aggr, zero agg) -> scatter(hW) -> gemm2.
// ---------------------------------------------------------------------------

#define MAXN 500000
#define NPAD 500032  // ntiles*64 rounding for fused agg-zero
__device__ float g_agg[(size_t)NPAD * 128];
__device__ float g_hw[(size_t)MAXN * 128];
// 4 images: [Win_hi, Win_lo, Wag_hi, Wag_lo], each [128n][64 uint] = f16x2[n][k]
__device__ __align__(16) unsigned int g_wimg[4 * 8192];

__device__ __forceinline__ float tanh_fast(float x) {
    float r; asm("tanh.approx.f32 %0, %1;" : "=f"(r) : "f"(x)); return r;
}
__device__ __forceinline__ uint32_t smem_u32(const void* p) {
    uint32_t a;
    asm("{ .reg .u64 t; cvta.to.shared.u64 t, %1; cvt.u32.u64 %0, t; }" : "=r"(a) : "l"(p));
    return a;
}
// hi = f16x2(a,b) (a in low half); lo = f16x2 of residuals.
__device__ __forceinline__ void pack2_split_f16(float a, float b, uint32_t& hi, uint32_t& lo) {
    asm("cvt.rn.f16x2.f32 %0, %1, %2;" : "=r"(hi) : "f"(b), "f"(a));
    __half2 h2 = *reinterpret_cast<__half2*>(&hi);
    float2 hf = __half22float2(h2);  // x = low (a part), y = high (b part)
    asm("cvt.rn.f16x2.f32 %0, %1, %2;" : "=r"(lo) : "f"(b - hf.y), "f"(a - hf.x));
}
// hi-only packing for A tiles.
__device__ __forceinline__ uint32_t pack2_hi_f16(float a, float b) {
    uint32_t hi;
    asm("cvt.rn.f16x2.f32 %0, %1, %2;" : "=r"(hi) : "f"(b), "f"(a));
    return hi;
}

#define LDSM_X4(r0, r1, r2, r3, addr) \
    asm volatile("ldmatrix.sync.aligned.m8n8.x4.shared.b16 {%0,%1,%2,%3}, [%4];" \
                 : "=r"(r0), "=r"(r1), "=r"(r2), "=r"(r3) : "r"(addr))

#define MMA16816(acc, a0, a1, a2, a3, b0, b1) \
    asm volatile("mma.sync.aligned.m16n8k16.row.col.f32.f16.f16.f32 " \
                 "{%0,%1,%2,%3}, {%4,%5,%6,%7}, {%8,%9}, {%0,%1,%2,%3};" \
                 : "+f"((acc)[0]), "+f"((acc)[1]), "+f"((acc)[2]), "+f"((acc)[3]) \
                 : "r"(a0), "r"(a1), "r"(a2), "r"(a3), "r"(b0), "r"(b1))

// smem layout: rows padded to 136 f16 (272 B) -> conflict-free ldmatrix.
#define ROWB 272u
#define ROWF 132                     // epilogue f32 stage row stride (528 B)
#define WIMGB (128u * ROWB)          // 34816 per W image
#define SM_WH 0u
#define SM_WL WIMGB                  // 34816
#define SM_AH (2u * WIMGB)           // 69632 (A hi image, 64 rows = 17408 B)
#define EPIB (64u * 132u * 4u)       // 33792 epilogue stage (overlays A region)
#define SM_TOTAL (SM_AH + EPIB)      // 103424 (101 KB) -> 2 CTAs/SM

// ---------------------------------------------------------------------------
// Kernel 0: build fp16 hi/lo W images (plain [n][k-pair] layout)
// ---------------------------------------------------------------------------
__global__ void prep_w(const float* __restrict__ Win, const float* __restrict__ Wag) {
    int n = blockIdx.x;     // output feature 0..127
    int kp = threadIdx.x;   // k-pair 0..63
    int k0 = kp * 2;
    float a0 = Win[k0 * 128 + n], a1 = Win[(k0 + 1) * 128 + n];
    float b0 = Wag[k0 * 128 + n], b1 = Wag[(k0 + 1) * 128 + n];
    uint32_t ahi, alo, bhi, blo;
    pack2_split_f16(a0, a1, ahi, alo);
    pack2_split_f16(b0, b1, bhi, blo);
    int idx = n * 64 + kp;
    g_wimg[0 * 8192 + idx] = ahi;
    g_wimg[1 * 8192 + idx] = alo;
    g_wimg[2 * 8192 + idx] = bhi;
    g_wimg[3 * 8192 + idx] = blo;
}

// ---------------------------------------------------------------------------
// Kernel 2: scatter-add  g_agg[dst] += g_hw[src]  (4 edges per warp, MLP=4)
// ---------------------------------------------------------------------------
__global__ void scatter_kernel(const int* __restrict__ src,
                               const int* __restrict__ dst, int E) {
    int warp = (blockIdx.x * blockDim.x + threadIdx.x) >> 5;
    int lane = threadIdx.x & 31;
    int e0 = warp * 4;
    if (e0 >= E) return;
    int s[4], d[4];
    float4 v[4];
    int cnt = (E - e0 < 4) ? (E - e0) : 4;
#pragma unroll
    for (int i = 0; i < 4; i++) {
        int e = (i < cnt) ? e0 + i : e0;
        s[i] = __ldg(&src[e]);
        d[i] = __ldg(&dst[e]);
    }
#pragma unroll
    for (int i = 0; i < 4; i++)
        v[i] = __ldg(reinterpret_cast<const float4*>(g_hw + (size_t)s[i] * 128) + lane);
#pragma unroll
    for (int i = 0; i < 4; i++) {
        if (i < cnt) {
            float* p = g_agg + (size_t)d[i] * 128 + lane * 4;
            asm volatile("red.global.add.v4.f32 [%0], {%1,%2,%3,%4};"
                         :: "l"(p), "f"(v[i].x), "f"(v[i].y), "f"(v[i].z), "f"(v[i].w)
                         : "memory");
        }
    }
}

// ---------------------------------------------------------------------------
// GEMM (persistent): CTA = 64 rows x 128 cols; warp tile 32x32 (grid 2x4).
// MODE 0: outp = A @ W, and zero g_agg slice    (gemm1: A=h, W=W_aggr pair)
// MODE 1: outp = tanh(A_m @ W + g_agg + m*bin + baggr)  (gemm2: A=x, W=W_in)
// fp16 2-term: per k-step 6 LDSM.x4 (A-hi 2, W-hi 2, W-lo 2) : 16 MMA.
// ---------------------------------------------------------------------------
template <int MODE>
__global__ void __launch_bounds__(256, 2) gemm_phase(
    const float* __restrict__ A, const unsigned int* __restrict__ wpair,
    const float* __restrict__ bin, const float* __restrict__ baggr,
    const int* __restrict__ mask, float* __restrict__ outp, int N, int ntiles) {
    extern __shared__ char smem[];
    const uint32_t sbase = smem_u32(smem);
    float* epi = reinterpret_cast<float*>(smem + SM_AH);  // post-k-loop overlay
    const int tid = threadIdx.x;
    const int wid = tid >> 5;
    const int lid = tid & 31;

    const float4* A4 = reinterpret_cast<const float4*>(A);
    const float4* agg4 = reinterpret_cast<const float4*>(g_agg);
    const long long max4 = (long long)N * 32 - 1;  // last valid float4 index

    // ---- hoisted bias registers (epilogue column block = tid&31, constant) ----
    float4 bi_r = make_float4(0.f, 0.f, 0.f, 0.f);
    float4 ba_r = make_float4(0.f, 0.f, 0.f, 0.f);
    if (MODE == 1) {
        bi_r = __ldg(reinterpret_cast<const float4*>(bin) + (tid & 31));
        ba_r = __ldg(reinterpret_cast<const float4*>(baggr) + (tid & 31));
    }

    // ---- prefetch A tile for first assigned tile (coalesced linear map) ----
    float4 av[8];
    float m8[8];
    {
        const long long base = (long long)blockIdx.x * 2048;
#pragma unroll
        for (int j = 0; j < 8; j++) {
            long long gi = base + (tid + 256 * j);
            av[j] = __ldg(A4 + (gi <= max4 ? gi : max4));
            if (MODE == 1) {
                int row = (int)(gi >> 5);
                m8[j] = (row < N && __ldg(&mask[row < N ? row : 0]) != 0) ? 1.f : 0.f;
            }
        }
    }

    // ---- copy W hi/lo pair into smem ONCE (persistent CTA) ----
    {
        const uint4* src = reinterpret_cast<const uint4*>(wpair);
#pragma unroll
        for (int it = 0; it < 16; it++) {
            int idx = tid + it * 256;        // 4096 uint4 (2 images)
            int row = idx >> 4;              // 0..255: img*128 + n
            int j = idx & 15;
            int img = row >> 7, n = row & 127;
            *reinterpret_cast<uint4*>(smem + SM_WH + (uint32_t)img * WIMGB +
                                      (uint32_t)n * ROWB + (uint32_t)j * 16) = src[idx];
        }
    }

    // warp tile: rows m0..m0+31, cols n0..n0+31
    const int wr = wid >> 2;       // 0..1
    const int wc = wid & 3;        // 0..3
    const int m0 = wr * 32;
    const int n0 = wc * 32;

    const int l8 = lid & 7;
    const int quad = lid >> 3;
    const uint32_t a_lane_off =
        (uint32_t)((m0 + l8 + (quad & 1) * 8) * ROWB + ((quad >> 1) * 8) * 2);
    const uint32_t b_lane_off =
        (uint32_t)((n0 + l8 + (quad >> 1) * 8) * ROWB + ((quad & 1) * 8) * 2);
    const uint32_t whi = sbase + SM_WH + b_lane_off;
    const uint32_t wlo = sbase + SM_WL + b_lane_off;
    const uint32_t ahb = sbase + SM_AH + a_lane_off;

    // acc->stage mapping
    const int tq = lid >> 2;   // 0..7
    const int t4 = lid & 3;    // 0..3

    for (int tile = blockIdx.x; tile < ntiles; tile += gridDim.x) {
        const int row0 = tile * 64;

        __syncthreads();  // epilogue stage reads done; W copy ordered (tile 0)

        // ---- convert + store A-hi tile from prefetched regs (mask folded) ----
#pragma unroll
        for (int j = 0; j < 8; j++) {
            int idx = tid + 256 * j;
            int row_l = idx >> 5;
            int c4 = idx & 31;
            float4 v = av[j];
            if (MODE == 1) { v.x *= m8[j]; v.y *= m8[j]; v.z *= m8[j]; v.w *= m8[j]; }
            uint2 hh;
            hh.x = pack2_hi_f16(v.x, v.y);
            hh.y = pack2_hi_f16(v.z, v.w);
            *reinterpret_cast<uint2*>(smem + SM_AH + (uint32_t)(row_l * ROWB + c4 * 8)) = hh;
        }

        // ---- MODE 0: zero this tile's g_agg slice (coalesced) ----
        if (MODE == 0) {
            float4* zp = reinterpret_cast<float4*>(g_agg) + (size_t)tile * 2048;
            const float4 z = make_float4(0.f, 0.f, 0.f, 0.f);
#pragma unroll
            for (int j = 0; j < 8; j++) zp[tid + j * 256] = z;
        }
        __syncthreads();

        // ---- prefetch NEXT tile's A (in flight during MMA + epilogue) ----
        {
            const int tn = tile + gridDim.x;
            if (tn < ntiles) {
                const long long base = (long long)tn * 2048;
#pragma unroll
                for (int j = 0; j < 8; j++) {
                    long long gi = base + (tid + 256 * j);
                    av[j] = __ldg(A4 + (gi <= max4 ? gi : max4));
                    if (MODE == 1) {
                        int row = (int)(gi >> 5);
                        m8[j] = (row < N && __ldg(&mask[row < N ? row : 0]) != 0)
                                    ? 1.f : 0.f;
                    }
                }
            }
        }

        // ---- accumulators ----
        float acc[2][4][4];
#pragma unroll
        for (int mt = 0; mt < 2; mt++)
#pragma unroll
            for (int nt = 0; nt < 4; nt++) {
                acc[mt][nt][0] = acc[mt][nt][1] = acc[mt][nt][2] = acc[mt][nt][3] = 0.f;
            }

        // ---- k-loop (8 k-steps): 6 LDSM, 16 MMA (hh + hl) ----
        {
            uint32_t fa[8], fbh[8], fbl[8];
#pragma unroll
            for (int ks = 0; ks < 8; ks++) {
                const uint32_t kb = (uint32_t)(ks * 32);
                LDSM_X4(fa[0], fa[1], fa[2], fa[3], ahb + kb);
                LDSM_X4(fa[4], fa[5], fa[6], fa[7], ahb + 16 * ROWB + kb);
                LDSM_X4(fbh[0], fbh[1], fbh[2], fbh[3], whi + kb);
                LDSM_X4(fbh[4], fbh[5], fbh[6], fbh[7], whi + 16 * ROWB + kb);
                LDSM_X4(fbl[0], fbl[1], fbl[2], fbl[3], wlo + kb);
                LDSM_X4(fbl[4], fbl[5], fbl[6], fbl[7], wlo + 16 * ROWB + kb);
#pragma unroll
                for (int nt = 0; nt < 4; nt++) {
                    MMA16816(acc[0][nt], fa[0], fa[1], fa[2], fa[3], fbh[2 * nt], fbh[2 * nt + 1]);
                    MMA16816(acc[1][nt], fa[4], fa[5], fa[6], fa[7], fbh[2 * nt], fbh[2 * nt + 1]);
                }
#pragma unroll
                for (int nt = 0; nt < 4; nt++) {
                    MMA16816(acc[0][nt], fa[0], fa[1], fa[2], fa[3], fbl[2 * nt], fbl[2 * nt + 1]);
                    MMA16816(acc[1][nt], fa[4], fa[5], fa[6], fa[7], fbl[2 * nt], fbl[2 * nt + 1]);
                }
            }
        }

        // ---- MODE 1: issue agg loads before staging (hidden under STS/sync) ----
        float4 ag[8];
        if (MODE == 1) {
#pragma unroll
            for (int j = 0; j < 8; j++) {
                long long gi = (long long)tile * 2048 + (tid + 256 * j);
                ag[j] = __ldg(agg4 + (gi <= max4 ? gi : max4));
            }
        }

        // ---- stage acc into smem (A region is dead after the k-loop) ----
        __syncthreads();
#pragma unroll
        for (int mt = 0; mt < 2; mt++) {
            const int rA = m0 + mt * 16 + tq;
#pragma unroll
            for (int nt = 0; nt < 4; nt++) {
                const int c = n0 + nt * 8 + 2 * t4;
                *reinterpret_cast<float2*>(&epi[rA * ROWF + c]) =
                    make_float2(acc[mt][nt][0], acc[mt][nt][1]);
                *reinterpret_cast<float2*>(&epi[(rA + 8) * ROWF + c]) =
                    make_float2(acc[mt][nt][2], acc[mt][nt][3]);
            }
        }
        __syncthreads();

        // ---- linear float4 epilogue (fully coalesced global traffic) ----
#pragma unroll
        for (int j = 0; j < 8; j++) {
            int idx = tid + 256 * j;
            int row_l = idx >> 5;
            int c4 = idx & 31;
            int rg = row0 + row_l;
            if (rg >= N) continue;
            float4 v = *reinterpret_cast<const float4*>(&epi[row_l * ROWF + c4 * 4]);
            size_t g4 = (size_t)rg * 32 + c4;
            if (MODE == 0) {
                reinterpret_cast<float4*>(outp)[g4] = v;
            } else {
                float mm = (__ldg(&mask[rg]) != 0) ? 1.f : 0.f;
                float4 o;
                o.x = tanh_fast(v.x + ag[j].x + mm * bi_r.x + ba_r.x);
                o.y = tanh_fast(v.y + ag[j].y + mm * bi_r.y + ba_r.y);
                o.z = tanh_fast(v.z + ag[j].z + mm * bi_r.z + ba_r.z);
                o.w = tanh_fast(v.w + ag[j].w + mm * bi_r.w + ba_r.w);
                reinterpret_cast<float4*>(outp)[g4] = o;
            }
        }
    }
}

// ---------------------------------------------------------------------------
// Launch
// ---------------------------------------------------------------------------
extern "C" void kernel_launch(void* const* d_in, const int* in_sizes, int n_in,
                              void* d_out, int out_size) {
    const float* x     = (const float*)d_in[0];
    const float* h     = (const float*)d_in[1];
    const float* Win   = (const float*)d_in[2];
    const float* bin   = (const float*)d_in[3];
    const float* Waggr = (const float*)d_in[4];
    const float* baggr = (const float*)d_in[5];
    const int* mask    = (const int*)d_in[6];
    const int* esrc    = (const int*)d_in[7];
    const int* edst    = (const int*)d_in[8];
    float* out = (float*)d_out;

    const int N = in_sizes[0] / 128;
    const int E = in_sizes[7];
    const int ntiles = (N + 63) / 64;

    static int smem_set = 0;
    if (!smem_set) {
        cudaFuncSetAttribute(gemm_phase<0>, cudaFuncAttributeMaxDynamicSharedMemorySize,
                             (int)SM_TOTAL);
        cudaFuncSetAttribute(gemm_phase<1>, cudaFuncAttributeMaxDynamicSharedMemorySize,
                             (int)SM_TOTAL);
        smem_set = 1;
    }

    unsigned int* wimg_dev = nullptr;
    cudaGetSymbolAddress((void**)&wimg_dev, g_wimg);
    float* hw_dev = nullptr;
    cudaGetSymbolAddress((void**)&hw_dev, g_hw);

    prep_w<<<128, 64>>>(Win, Waggr);
    // gemm1: hW = h @ W_aggr (images 2,3); also zeroes g_agg
    gemm_phase<0><<<296, 256, SM_TOTAL>>>(h, wimg_dev + 2 * 8192, nullptr, nullptr,
                                          nullptr, hw_dev, N, ntiles);
    // scatter: g_agg[dst] += hW[src]
    const int warps_needed = (E + 3) / 4;
    scatter_kernel<<<(warps_needed + 7) / 8, 256>>>(esrc, edst, E);
    // gemm2: out = tanh(x_m @ W_in + g_agg + m*b_in + b_aggr)   (images 0,1)
    gemm_phase<1><<<296, 256, SM_TOTAL>>>(x, wimg_dev, bin, baggr, mask, out, N,
                                          ntiles);
}

// round 16
// speedup vs baseline: 1.4949x; 1.0457x over previous
#include <cuda_runtime.h>
#include <cuda_fp16.h>
#include <cstdint>
#include <cstddef>

// ---------------------------------------------------------------------------
// TreeRNNCell: out = tanh( mask*(x@W_in + b_in) + segsum(h[src]->dst)@W_aggr + b_aggr )
// N = 500000, E = 500000, X = H = 128.
//
// R15: R14 + hW intermediate stored as fp16x2 (was f32):
//   gemm0 writes 128 MB instead of 256; scatter reads 128 MB instead of 256.
//   Scatter unpacks f16->f32 and accumulates with red.global.add.v4.f32.
// Pipeline: prep_w -> gemm1(hW=h@W_aggr f16, zero agg) -> scatter -> gemm2.
// ---------------------------------------------------------------------------

#define MAXN 500000
#define NPAD 500032  // ntiles*64 rounding for fused agg-zero
__device__ float g_agg[(size_t)NPAD * 128];
__device__ __align__(16) uint2 g_hw[(size_t)MAXN * 32];   // fp16x2: 32 uint2/row
// 4 images: [Win_hi, Win_lo, Wag_hi, Wag_lo], each [128n][64 uint] = f16x2[n][k]
__device__ __align__(16) unsigned int g_wimg[4 * 8192];

__device__ __forceinline__ float tanh_fast(float x) {
    float r; asm("tanh.approx.f32 %0, %1;" : "=f"(r) : "f"(x)); return r;
}
__device__ __forceinline__ uint32_t smem_u32(const void* p) {
    uint32_t a;
    asm("{ .reg .u64 t; cvta.to.shared.u64 t, %1; cvt.u32.u64 %0, t; }" : "=r"(a) : "l"(p));
    return a;
}
// hi = f16x2(a,b) (a in low half); lo = f16x2 of residuals.
__device__ __forceinline__ void pack2_split_f16(float a, float b, uint32_t& hi, uint32_t& lo) {
    asm("cvt.rn.f16x2.f32 %0, %1, %2;" : "=r"(hi) : "f"(b), "f"(a));
    __half2 h2 = *reinterpret_cast<__half2*>(&hi);
    float2 hf = __half22float2(h2);  // x = low (a part), y = high (b part)
    asm("cvt.rn.f16x2.f32 %0, %1, %2;" : "=r"(lo) : "f"(b - hf.y), "f"(a - hf.x));
}
// hi-only packing.
__device__ __forceinline__ uint32_t pack2_hi_f16(float a, float b) {
    uint32_t hi;
    asm("cvt.rn.f16x2.f32 %0, %1, %2;" : "=r"(hi) : "f"(b), "f"(a));
    return hi;
}

#define LDSM_X4(r0, r1, r2, r3, addr) \
    asm volatile("ldmatrix.sync.aligned.m8n8.x4.shared.b16 {%0,%1,%2,%3}, [%4];" \
                 : "=r"(r0), "=r"(r1), "=r"(r2), "=r"(r3) : "r"(addr))

#define MMA16816(acc, a0, a1, a2, a3, b0, b1) \
    asm volatile("mma.sync.aligned.m16n8k16.row.col.f32.f16.f16.f32 " \
                 "{%0,%1,%2,%3}, {%4,%5,%6,%7}, {%8,%9}, {%0,%1,%2,%3};" \
                 : "+f"((acc)[0]), "+f"((acc)[1]), "+f"((acc)[2]), "+f"((acc)[3]) \
                 : "r"(a0), "r"(a1), "r"(a2), "r"(a3), "r"(b0), "r"(b1))

// smem layout: rows padded to 136 f16 (272 B) -> conflict-free ldmatrix.
#define ROWB 272u
#define ROWF 132                     // epilogue f32 stage row stride (528 B)
#define WIMGB (128u * ROWB)          // 34816 per W image
#define SM_WH 0u
#define SM_WL WIMGB                  // 34816
#define SM_AH (2u * WIMGB)           // 69632 (A hi image, 64 rows = 17408 B)
#define EPIB (64u * 132u * 4u)       // 33792 epilogue stage (overlays A region)
#define SM_TOTAL (SM_AH + EPIB)      // 103424 (101 KB) -> 2 CTAs/SM

// ---------------------------------------------------------------------------
// Kernel 0: build fp16 hi/lo W images (plain [n][k-pair] layout)
// ---------------------------------------------------------------------------
__global__ void prep_w(const float* __restrict__ Win, const float* __restrict__ Wag) {
    int n = blockIdx.x;     // output feature 0..127
    int kp = threadIdx.x;   // k-pair 0..63
    int k0 = kp * 2;
    float a0 = Win[k0 * 128 + n], a1 = Win[(k0 + 1) * 128 + n];
    float b0 = Wag[k0 * 128 + n], b1 = Wag[(k0 + 1) * 128 + n];
    uint32_t ahi, alo, bhi, blo;
    pack2_split_f16(a0, a1, ahi, alo);
    pack2_split_f16(b0, b1, bhi, blo);
    int idx = n * 64 + kp;
    g_wimg[0 * 8192 + idx] = ahi;
    g_wimg[1 * 8192 + idx] = alo;
    g_wimg[2 * 8192 + idx] = bhi;
    g_wimg[3 * 8192 + idx] = blo;
}

// ---------------------------------------------------------------------------
// Kernel 2: scatter-add  g_agg[dst] += f32(g_hw[src])  (4 edges/warp, MLP=4)
// ---------------------------------------------------------------------------
__global__ void scatter_kernel(const int* __restrict__ src,
                               const int* __restrict__ dst, int E) {
    int warp = (blockIdx.x * blockDim.x + threadIdx.x) >> 5;
    int lane = threadIdx.x & 31;
    int e0 = warp * 4;
    if (e0 >= E) return;
    int s[4], d[4];
    uint2 v[4];
    int cnt = (E - e0 < 4) ? (E - e0) : 4;
#pragma unroll
    for (int i = 0; i < 4; i++) {
        int e = (i < cnt) ? e0 + i : e0;
        s[i] = __ldg(&src[e]);
        d[i] = __ldg(&dst[e]);
    }
#pragma unroll
    for (int i = 0; i < 4; i++)
        v[i] = __ldg(g_hw + (size_t)s[i] * 32 + lane);
#pragma unroll
    for (int i = 0; i < 4; i++) {
        if (i < cnt) {
            float2 f01 = __half22float2(*reinterpret_cast<__half2*>(&v[i].x));
            float2 f23 = __half22float2(*reinterpret_cast<__half2*>(&v[i].y));
            float* p = g_agg + (size_t)d[i] * 128 + lane * 4;
            asm volatile("red.global.add.v4.f32 [%0], {%1,%2,%3,%4};"
                         :: "l"(p), "f"(f01.x), "f"(f01.y), "f"(f23.x), "f"(f23.y)
                         : "memory");
        }
    }
}

// ---------------------------------------------------------------------------
// GEMM (persistent): CTA = 64 rows x 128 cols; warp tile 32x32 (grid 2x4).
// MODE 0: g_hw = f16(A @ W), and zero g_agg slice  (gemm1: A=h, W=W_aggr)
// MODE 1: outp = tanh(A_m @ W + g_agg + m*bin + baggr)  (gemm2: A=x, W=W_in)
// fp16 2-term: per k-step 6 LDSM.x4 (A-hi 2, W-hi 2, W-lo 2) : 16 MMA.
// ---------------------------------------------------------------------------
template <int MODE>
__global__ void __launch_bounds__(256, 2) gemm_phase(
    const float* __restrict__ A, const unsigned int* __restrict__ wpair,
    const float* __restrict__ bin, const float* __restrict__ baggr,
    const int* __restrict__ mask, float* __restrict__ outp, int N, int ntiles) {
    extern __shared__ char smem[];
    const uint32_t sbase = smem_u32(smem);
    float* epi = reinterpret_cast<float*>(smem + SM_AH);  // post-k-loop overlay
    const int tid = threadIdx.x;
    const int wid = tid >> 5;
    const int lid = tid & 31;

    const float4* A4 = reinterpret_cast<const float4*>(A);
    const float4* agg4 = reinterpret_cast<const float4*>(g_agg);
    const long long max4 = (long long)N * 32 - 1;  // last valid float4 index

    // ---- hoisted bias registers (epilogue column block = tid&31, constant) ----
    float4 bi_r = make_float4(0.f, 0.f, 0.f, 0.f);
    float4 ba_r = make_float4(0.f, 0.f, 0.f, 0.f);
    if (MODE == 1) {
        bi_r = __ldg(reinterpret_cast<const float4*>(bin) + (tid & 31));
        ba_r = __ldg(reinterpret_cast<const float4*>(baggr) + (tid & 31));
    }

    // ---- prefetch A tile for first assigned tile (coalesced linear map) ----
    float4 av[8];
    float m8[8];
    {
        const long long base = (long long)blockIdx.x * 2048;
#pragma unroll
        for (int j = 0; j < 8; j++) {
            long long gi = base + (tid + 256 * j);
            av[j] = __ldg(A4 + (gi <= max4 ? gi : max4));
            if (MODE == 1) {
                int row = (int)(gi >> 5);
                m8[j] = (row < N && __ldg(&mask[row < N ? row : 0]) != 0) ? 1.f : 0.f;
            }
        }
    }

    // ---- copy W hi/lo pair into smem ONCE (persistent CTA) ----
    {
        const uint4* src = reinterpret_cast<const uint4*>(wpair);
#pragma unroll
        for (int it = 0; it < 16; it++) {
            int idx = tid + it * 256;        // 4096 uint4 (2 images)
            int row = idx >> 4;              // 0..255: img*128 + n
            int j = idx & 15;
            int img = row >> 7, n = row & 127;
            *reinterpret_cast<uint4*>(smem + SM_WH + (uint32_t)img * WIMGB +
                                      (uint32_t)n * ROWB + (uint32_t)j * 16) = src[idx];
        }
    }

    // warp tile: rows m0..m0+31, cols n0..n0+31
    const int wr = wid >> 2;       // 0..1
    const int wc = wid & 3;        // 0..3
    const int m0 = wr * 32;
    const int n0 = wc * 32;

    const int l8 = lid & 7;
    const int quad = lid >> 3;
    const uint32_t a_lane_off =
        (uint32_t)((m0 + l8 + (quad & 1) * 8) * ROWB + ((quad >> 1) * 8) * 2);
    const uint32_t b_lane_off =
        (uint32_t)((n0 + l8 + (quad >> 1) * 8) * ROWB + ((quad & 1) * 8) * 2);
    const uint32_t whi = sbase + SM_WH + b_lane_off;
    const uint32_t wlo = sbase + SM_WL + b_lane_off;
    const uint32_t ahb = sbase + SM_AH + a_lane_off;

    // acc->stage mapping
    const int tq = lid >> 2;   // 0..7
    const int t4 = lid & 3;    // 0..3

    for (int tile = blockIdx.x; tile < ntiles; tile += gridDim.x) {
        const int row0 = tile * 64;

        __syncthreads();  // epilogue stage reads done; W copy ordered (tile 0)

        // ---- convert + store A-hi tile from prefetched regs (mask folded) ----
#pragma unroll
        for (int j = 0; j < 8; j++) {
            int idx = tid + 256 * j;
            int row_l = idx >> 5;
            int c4 = idx & 31;
            float4 v = av[j];
            if (MODE == 1) { v.x *= m8[j]; v.y *= m8[j]; v.z *= m8[j]; v.w *= m8[j]; }
            uint2 hh;
            hh.x = pack2_hi_f16(v.x, v.y);
            hh.y = pack2_hi_f16(v.z, v.w);
            *reinterpret_cast<uint2*>(smem + SM_AH + (uint32_t)(row_l * ROWB + c4 * 8)) = hh;
        }

        // ---- MODE 0: zero this tile's g_agg slice (coalesced) ----
        if (MODE == 0) {
            float4* zp = reinterpret_cast<float4*>(g_agg) + (size_t)tile * 2048;
            const float4 z = make_float4(0.f, 0.f, 0.f, 0.f);
#pragma unroll
            for (int j = 0; j < 8; j++) zp[tid + j * 256] = z;
        }
        __syncthreads();

        // ---- prefetch NEXT tile's A (in flight during MMA + epilogue) ----
        {
            const int tn = tile + gridDim.x;
            if (tn < ntiles) {
                const long long base = (long long)tn * 2048;
#pragma unroll
                for (int j = 0; j < 8; j++) {
                    long long gi = base + (tid + 256 * j);
                    av[j] = __ldg(A4 + (gi <= max4 ? gi : max4));
                    if (MODE == 1) {
                        int row = (int)(gi >> 5);
                        m8[j] = (row < N && __ldg(&mask[row < N ? row : 0]) != 0)
                                    ? 1.f : 0.f;
                    }
                }
            }
        }

        // ---- accumulators ----
        float acc[2][4][4];
#pragma unroll
        for (int mt = 0; mt < 2; mt++)
#pragma unroll
            for (int nt = 0; nt < 4; nt++) {
                acc[mt][nt][0] = acc[mt][nt][1] = acc[mt][nt][2] = acc[mt][nt][3] = 0.f;
            }

        // ---- k-loop (8 k-steps): 6 LDSM, 16 MMA (hh + hl) ----
        {
            uint32_t fa[8], fbh[8], fbl[8];
#pragma unroll
            for (int ks = 0; ks < 8; ks++) {
                const uint32_t kb = (uint32_t)(ks * 32);
                LDSM_X4(fa[0], fa[1], fa[2], fa[3], ahb + kb);
                LDSM_X4(fa[4], fa[5], fa[6], fa[7], ahb + 16 * ROWB + kb);
                LDSM_X4(fbh[0], fbh[1], fbh[2], fbh[3], whi + kb);
                LDSM_X4(fbh[4], fbh[5], fbh[6], fbh[7], whi + 16 * ROWB + kb);
                LDSM_X4(fbl[0], fbl[1], fbl[2], fbl[3], wlo + kb);
                LDSM_X4(fbl[4], fbl[5], fbl[6], fbl[7], wlo + 16 * ROWB + kb);
#pragma unroll
                for (int nt = 0; nt < 4; nt++) {
                    MMA16816(acc[0][nt], fa[0], fa[1], fa[2], fa[3], fbh[2 * nt], fbh[2 * nt + 1]);
                    MMA16816(acc[1][nt], fa[4], fa[5], fa[6], fa[7], fbh[2 * nt], fbh[2 * nt + 1]);
                }
#pragma unroll
                for (int nt = 0; nt < 4; nt++) {
                    MMA16816(acc[0][nt], fa[0], fa[1], fa[2], fa[3], fbl[2 * nt], fbl[2 * nt + 1]);
                    MMA16816(acc[1][nt], fa[4], fa[5], fa[6], fa[7], fbl[2 * nt], fbl[2 * nt + 1]);
                }
            }
        }

        // ---- MODE 1: issue agg loads before staging (hidden under STS/sync) ----
        float4 ag[8];
        if (MODE == 1) {
#pragma unroll
            for (int j = 0; j < 8; j++) {
                long long gi = (long long)tile * 2048 + (tid + 256 * j);
                ag[j] = __ldg(agg4 + (gi <= max4 ? gi : max4));
            }
        }

        // ---- stage acc into smem (A region is dead after the k-loop) ----
        __syncthreads();
#pragma unroll
        for (int mt = 0; mt < 2; mt++) {
            const int rA = m0 + mt * 16 + tq;
#pragma unroll
            for (int nt = 0; nt < 4; nt++) {
                const int c = n0 + nt * 8 + 2 * t4;
                *reinterpret_cast<float2*>(&epi[rA * ROWF + c]) =
                    make_float2(acc[mt][nt][0], acc[mt][nt][1]);
                *reinterpret_cast<float2*>(&epi[(rA + 8) * ROWF + c]) =
                    make_float2(acc[mt][nt][2], acc[mt][nt][3]);
            }
        }
        __syncthreads();

        // ---- linear epilogue (fully coalesced global traffic) ----
#pragma unroll
        for (int j = 0; j < 8; j++) {
            int idx = tid + 256 * j;
            int row_l = idx >> 5;
            int c4 = idx & 31;
            int rg = row0 + row_l;
            if (rg >= N) continue;
            float4 v = *reinterpret_cast<const float4*>(&epi[row_l * ROWF + c4 * 4]);
            if (MODE == 0) {
                uint2 hv;
                hv.x = pack2_hi_f16(v.x, v.y);
                hv.y = pack2_hi_f16(v.z, v.w);
                g_hw[(size_t)rg * 32 + c4] = hv;
            } else {
                size_t g4 = (size_t)rg * 32 + c4;
                float mm = (__ldg(&mask[rg]) != 0) ? 1.f : 0.f;
                float4 o;
                o.x = tanh_fast(v.x + ag[j].x + mm * bi_r.x + ba_r.x);
                o.y = tanh_fast(v.y + ag[j].y + mm * bi_r.y + ba_r.y);
                o.z = tanh_fast(v.z + ag[j].z + mm * bi_r.z + ba_r.z);
                o.w = tanh_fast(v.w + ag[j].w + mm * bi_r.w + ba_r.w);
                reinterpret_cast<float4*>(outp)[g4] = o;
            }
        }
    }
}

// ---------------------------------------------------------------------------
// Launch
// ---------------------------------------------------------------------------
extern "C" void kernel_launch(void* const* d_in, const int* in_sizes, int n_in,
                              void* d_out, int out_size) {
    const float* x     = (const float*)d_in[0];
    const float* h     = (const float*)d_in[1];
    const float* Win   = (const float*)d_in[2];
    const float* bin   = (const float*)d_in[3];
    const float* Waggr = (const float*)d_in[4];
    const float* baggr = (const float*)d_in[5];
    const int* mask    = (const int*)d_in[6];
    const int* esrc    = (const int*)d_in[7];
    const int* edst    = (const int*)d_in[8];
    float* out = (float*)d_out;

    const int N = in_sizes[0] / 128;
    const int E = in_sizes[7];
    const int ntiles = (N + 63) / 64;

    static int smem_set = 0;
    if (!smem_set) {
        cudaFuncSetAttribute(gemm_phase<0>, cudaFuncAttributeMaxDynamicSharedMemorySize,
                             (int)SM_TOTAL);
        cudaFuncSetAttribute(gemm_phase<1>, cudaFuncAttributeMaxDynamicSharedMemorySize,
                             (int)SM_TOTAL);
        smem_set = 1;
    }

    unsigned int* wimg_dev = nullptr;
    cudaGetSymbolAddress((void**)&wimg_dev, g_wimg);

    prep_w<<<128, 64>>>(Win, Waggr);
    // gemm1: g_hw = f16(h @ W_aggr) (images 2,3); also zeroes g_agg
    gemm_phase<0><<<296, 256, SM_TOTAL>>>(h, wimg_dev + 2 * 8192, nullptr, nullptr,
                                          nullptr, nullptr, N, ntiles);
    // scatter: g_agg[dst] += f32(g_hw[src])
    const int warps_needed = (E + 3) / 4;
    scatter_kernel<<<(warps_needed + 7) / 8, 256>>>(esrc, edst, E);
    // gemm2: out = tanh(x_m @ W_in + g_agg + m*b_in + b_aggr)   (images 0,1)
    gemm_phase<1><<<296, 256, SM_TOTAL>>>(x, wimg_dev, bin, baggr, mask, out, N,
                                          ntiles);
}

// round 17
// speedup vs baseline: 1.5368x; 1.0280x over previous
#include <cuda_runtime.h>
#include <cuda_fp16.h>
#include <cstdint>
#include <cstddef>

// ---------------------------------------------------------------------------
// TreeRNNCell: out = tanh( mask*(x@W_in + b_in) + segsum(h[src]->dst)@W_aggr + b_aggr )
// N = 500000, E = 500000, X = H = 128.
//
// R16: gemm0 computes hW hi-only (output is fp16-rounded anyway):
//   8 MMA / 4 LDSM per k-step, W smem halves -> 68.6 KB -> 3 CTAs/SM.
//   gemm1 keeps the 2-term (hh+hl) product and 2 CTAs/SM.
// Pipeline: prep_w -> gemm0(hW=f16(h@Wag_hi), zero agg) -> scatter -> gemm1.
// ---------------------------------------------------------------------------

#define MAXN 500000
#define NPAD 500032
__device__ float g_agg[(size_t)NPAD * 128];
__device__ __align__(16) uint2 g_hw[(size_t)MAXN * 32];   // fp16x2: 32 uint2/row
// 4 images: [Win_hi, Win_lo, Wag_hi, Wag_lo], each [128n][64 uint] = f16x2[n][k]
__device__ __align__(16) unsigned int g_wimg[4 * 8192];

__device__ __forceinline__ float tanh_fast(float x) {
    float r; asm("tanh.approx.f32 %0, %1;" : "=f"(r) : "f"(x)); return r;
}
__device__ __forceinline__ uint32_t smem_u32(const void* p) {
    uint32_t a;
    asm("{ .reg .u64 t; cvta.to.shared.u64 t, %1; cvt.u32.u64 %0, t; }" : "=r"(a) : "l"(p));
    return a;
}
__device__ __forceinline__ void pack2_split_f16(float a, float b, uint32_t& hi, uint32_t& lo) {
    asm("cvt.rn.f16x2.f32 %0, %1, %2;" : "=r"(hi) : "f"(b), "f"(a));
    __half2 h2 = *reinterpret_cast<__half2*>(&hi);
    float2 hf = __half22float2(h2);
    asm("cvt.rn.f16x2.f32 %0, %1, %2;" : "=r"(lo) : "f"(b - hf.y), "f"(a - hf.x));
}
__device__ __forceinline__ uint32_t pack2_hi_f16(float a, float b) {
    uint32_t hi;
    asm("cvt.rn.f16x2.f32 %0, %1, %2;" : "=r"(hi) : "f"(b), "f"(a));
    return hi;
}

#define LDSM_X4(r0, r1, r2, r3, addr) \
    asm volatile("ldmatrix.sync.aligned.m8n8.x4.shared.b16 {%0,%1,%2,%3}, [%4];" \
                 : "=r"(r0), "=r"(r1), "=r"(r2), "=r"(r3) : "r"(addr))

#define MMA16816(acc, a0, a1, a2, a3, b0, b1) \
    asm volatile("mma.sync.aligned.m16n8k16.row.col.f32.f16.f16.f32 " \
                 "{%0,%1,%2,%3}, {%4,%5,%6,%7}, {%8,%9}, {%0,%1,%2,%3};" \
                 : "+f"((acc)[0]), "+f"((acc)[1]), "+f"((acc)[2]), "+f"((acc)[3]) \
                 : "r"(a0), "r"(a1), "r"(a2), "r"(a3), "r"(b0), "r"(b1))

// smem: rows padded to 136 f16 (272 B) -> conflict-free ldmatrix.
#define ROWB 272u
#define ROWF 132
#define WIMGB (128u * ROWB)          // 34816 per W image
#define EPIB (64u * 132u * 4u)       // 33792 epilogue stage

// gemm1 (2-term): W hi+lo + A + epi
#define S1_WH 0u
#define S1_WL WIMGB
#define S1_A (2u * WIMGB)            // 69632
#define S1_TOTAL (S1_A + EPIB)       // 103424 -> 2 CTAs/SM

// gemm0 (hi-only): W hi + A/epi overlay
#define S0_WH 0u
#define S0_A WIMGB                   // 34816
#define S0_TOTAL (S0_A + EPIB)       // 68608 -> 3 CTAs/SM

// ---------------------------------------------------------------------------
// Kernel 0: build fp16 hi/lo W images
// ---------------------------------------------------------------------------
__global__ void prep_w(const float* __restrict__ Win, const float* __restrict__ Wag) {
    int n = blockIdx.x;
    int kp = threadIdx.x;
    int k0 = kp * 2;
    float a0 = Win[k0 * 128 + n], a1 = Win[(k0 + 1) * 128 + n];
    float b0 = Wag[k0 * 128 + n], b1 = Wag[(k0 + 1) * 128 + n];
    uint32_t ahi, alo, bhi, blo;
    pack2_split_f16(a0, a1, ahi, alo);
    pack2_split_f16(b0, b1, bhi, blo);
    int idx = n * 64 + kp;
    g_wimg[0 * 8192 + idx] = ahi;
    g_wimg[1 * 8192 + idx] = alo;
    g_wimg[2 * 8192 + idx] = bhi;
    g_wimg[3 * 8192 + idx] = blo;
}

// ---------------------------------------------------------------------------
// scatter-add  g_agg[dst] += f32(g_hw[src])  (4 edges/warp, MLP=4)
// ---------------------------------------------------------------------------
__global__ void scatter_kernel(const int* __restrict__ src,
                               const int* __restrict__ dst, int E) {
    int warp = (blockIdx.x * blockDim.x + threadIdx.x) >> 5;
    int lane = threadIdx.x & 31;
    int e0 = warp * 4;
    if (e0 >= E) return;
    int s[4], d[4];
    uint2 v[4];
    int cnt = (E - e0 < 4) ? (E - e0) : 4;
#pragma unroll
    for (int i = 0; i < 4; i++) {
        int e = (i < cnt) ? e0 + i : e0;
        s[i] = __ldg(&src[e]);
        d[i] = __ldg(&dst[e]);
    }
#pragma unroll
    for (int i = 0; i < 4; i++)
        v[i] = __ldg(g_hw + (size_t)s[i] * 32 + lane);
#pragma unroll
    for (int i = 0; i < 4; i++) {
        if (i < cnt) {
            float2 f01 = __half22float2(*reinterpret_cast<__half2*>(&v[i].x));
            float2 f23 = __half22float2(*reinterpret_cast<__half2*>(&v[i].y));
            float* p = g_agg + (size_t)d[i] * 128 + lane * 4;
            asm volatile("red.global.add.v4.f32 [%0], {%1,%2,%3,%4};"
                         :: "l"(p), "f"(f01.x), "f"(f01.y), "f"(f23.x), "f"(f23.y)
                         : "memory");
        }
    }
}

// ---------------------------------------------------------------------------
// gemm0 (persistent, 3 CTAs/SM): g_hw = f16(h @ Wag_hi); zero g_agg slice.
// hi-only: per k-step 4 LDSM.x4, 8 MMA. Prefetch after k-loop (short av range).
// ---------------------------------------------------------------------------
__global__ void __launch_bounds__(256, 3) gemm0_kernel(
    const float* __restrict__ A, const unsigned int* __restrict__ whi_img,
    int N, int ntiles) {
    extern __shared__ char smem[];
    const uint32_t sbase = smem_u32(smem);
    float* epi = reinterpret_cast<float*>(smem + S0_A);
    const int tid = threadIdx.x;
    const int wid = tid >> 5;
    const int lid = tid & 31;

    const float4* A4 = reinterpret_cast<const float4*>(A);
    const long long max4 = (long long)N * 32 - 1;

    // ---- copy W hi image into smem ONCE ----
    {
        const uint4* src = reinterpret_cast<const uint4*>(whi_img);
#pragma unroll
        for (int it = 0; it < 8; it++) {
            int idx = tid + it * 256;        // 2048 uint4
            int n = idx >> 4;
            int j = idx & 15;
            *reinterpret_cast<uint4*>(smem + S0_WH + (uint32_t)n * ROWB +
                                      (uint32_t)j * 16) = src[idx];
        }
    }

    const int wr = wid >> 2;
    const int wc = wid & 3;
    const int m0 = wr * 32;
    const int n0 = wc * 32;
    const int l8 = lid & 7;
    const int quad = lid >> 3;
    const uint32_t a_lane_off =
        (uint32_t)((m0 + l8 + (quad & 1) * 8) * ROWB + ((quad >> 1) * 8) * 2);
    const uint32_t b_lane_off =
        (uint32_t)((n0 + l8 + (quad >> 1) * 8) * ROWB + ((quad & 1) * 8) * 2);
    const uint32_t whi = sbase + S0_WH + b_lane_off;
    const uint32_t ahb = sbase + S0_A + a_lane_off;
    const int tq = lid >> 2;
    const int t4 = lid & 3;

    // prefetch first tile
    float4 av[8];
    {
        const long long base = (long long)blockIdx.x * 2048;
#pragma unroll
        for (int j = 0; j < 8; j++) {
            long long gi = base + (tid + 256 * j);
            av[j] = __ldg(A4 + (gi <= max4 ? gi : max4));
        }
    }

    for (int tile = blockIdx.x; tile < ntiles; tile += gridDim.x) {
        const int row0 = tile * 64;

        __syncthreads();  // prev epilogue reads done; W copy ordered (tile 0)

        // convert + store A-hi tile
#pragma unroll
        for (int j = 0; j < 8; j++) {
            int idx = tid + 256 * j;
            int row_l = idx >> 5;
            int c4 = idx & 31;
            uint2 hh;
            hh.x = pack2_hi_f16(av[j].x, av[j].y);
            hh.y = pack2_hi_f16(av[j].z, av[j].w);
            *reinterpret_cast<uint2*>(smem + S0_A + (uint32_t)(row_l * ROWB + c4 * 8)) = hh;
        }

        // zero this tile's g_agg slice
        {
            float4* zp = reinterpret_cast<float4*>(g_agg) + (size_t)tile * 2048;
            const float4 z = make_float4(0.f, 0.f, 0.f, 0.f);
#pragma unroll
            for (int j = 0; j < 8; j++) zp[tid + j * 256] = z;
        }
        __syncthreads();

        float acc[2][4][4];
#pragma unroll
        for (int mt = 0; mt < 2; mt++)
#pragma unroll
            for (int nt = 0; nt < 4; nt++) {
                acc[mt][nt][0] = acc[mt][nt][1] = acc[mt][nt][2] = acc[mt][nt][3] = 0.f;
            }

        // k-loop: 4 LDSM, 8 MMA per k-step
        {
            uint32_t fa[8], fbh[8];
#pragma unroll
            for (int ks = 0; ks < 8; ks++) {
                const uint32_t kb = (uint32_t)(ks * 32);
                LDSM_X4(fa[0], fa[1], fa[2], fa[3], ahb + kb);
                LDSM_X4(fa[4], fa[5], fa[6], fa[7], ahb + 16 * ROWB + kb);
                LDSM_X4(fbh[0], fbh[1], fbh[2], fbh[3], whi + kb);
                LDSM_X4(fbh[4], fbh[5], fbh[6], fbh[7], whi + 16 * ROWB + kb);
#pragma unroll
                for (int nt = 0; nt < 4; nt++) {
                    MMA16816(acc[0][nt], fa[0], fa[1], fa[2], fa[3], fbh[2 * nt], fbh[2 * nt + 1]);
                    MMA16816(acc[1][nt], fa[4], fa[5], fa[6], fa[7], fbh[2 * nt], fbh[2 * nt + 1]);
                }
            }
        }

        // prefetch next tile (hidden under staging + epilogue)
        {
            const int tn = tile + gridDim.x;
            if (tn < ntiles) {
                const long long base = (long long)tn * 2048;
#pragma unroll
                for (int j = 0; j < 8; j++) {
                    long long gi = base + (tid + 256 * j);
                    av[j] = __ldg(A4 + (gi <= max4 ? gi : max4));
                }
            }
        }

        // stage acc -> epi (A region dead)
        __syncthreads();
#pragma unroll
        for (int mt = 0; mt < 2; mt++) {
            const int rA = m0 + mt * 16 + tq;
#pragma unroll
            for (int nt = 0; nt < 4; nt++) {
                const int c = n0 + nt * 8 + 2 * t4;
                *reinterpret_cast<float2*>(&epi[rA * ROWF + c]) =
                    make_float2(acc[mt][nt][0], acc[mt][nt][1]);
                *reinterpret_cast<float2*>(&epi[(rA + 8) * ROWF + c]) =
                    make_float2(acc[mt][nt][2], acc[mt][nt][3]);
            }
        }
        __syncthreads();

        // linear epilogue: pack f16 -> g_hw
#pragma unroll
        for (int j = 0; j < 8; j++) {
            int idx = tid + 256 * j;
            int row_l = idx >> 5;
            int c4 = idx & 31;
            int rg = row0 + row_l;
            if (rg >= N) continue;
            float4 v = *reinterpret_cast<const float4*>(&epi[row_l * ROWF + c4 * 4]);
            uint2 hv;
            hv.x = pack2_hi_f16(v.x, v.y);
            hv.y = pack2_hi_f16(v.z, v.w);
            g_hw[(size_t)rg * 32 + c4] = hv;
        }
    }
}

// ---------------------------------------------------------------------------
// gemm1 (persistent, 2 CTAs/SM): out = tanh(x_m@W_in(hh+hl) + agg + biases)
// ---------------------------------------------------------------------------
__global__ void __launch_bounds__(256, 2) gemm1_kernel(
    const float* __restrict__ A, const unsigned int* __restrict__ wpair,
    const float* __restrict__ bin, const float* __restrict__ baggr,
    const int* __restrict__ mask, float* __restrict__ outp, int N, int ntiles) {
    extern __shared__ char smem[];
    const uint32_t sbase = smem_u32(smem);
    float* epi = reinterpret_cast<float*>(smem + S1_A);
    const int tid = threadIdx.x;
    const int wid = tid >> 5;
    const int lid = tid & 31;

    const float4* A4 = reinterpret_cast<const float4*>(A);
    const float4* agg4 = reinterpret_cast<const float4*>(g_agg);
    const long long max4 = (long long)N * 32 - 1;

    float4 bi_r = __ldg(reinterpret_cast<const float4*>(bin) + (tid & 31));
    float4 ba_r = __ldg(reinterpret_cast<const float4*>(baggr) + (tid & 31));

    float4 av[8];
    float m8[8];
    {
        const long long base = (long long)blockIdx.x * 2048;
#pragma unroll
        for (int j = 0; j < 8; j++) {
            long long gi = base + (tid + 256 * j);
            av[j] = __ldg(A4 + (gi <= max4 ? gi : max4));
            int row = (int)(gi >> 5);
            m8[j] = (row < N && __ldg(&mask[row < N ? row : 0]) != 0) ? 1.f : 0.f;
        }
    }

    {
        const uint4* src = reinterpret_cast<const uint4*>(wpair);
#pragma unroll
        for (int it = 0; it < 16; it++) {
            int idx = tid + it * 256;
            int row = idx >> 4;
            int j = idx & 15;
            int img = row >> 7, n = row & 127;
            *reinterpret_cast<uint4*>(smem + S1_WH + (uint32_t)img * WIMGB +
                                      (uint32_t)n * ROWB + (uint32_t)j * 16) = src[idx];
        }
    }

    const int wr = wid >> 2;
    const int wc = wid & 3;
    const int m0 = wr * 32;
    const int n0 = wc * 32;
    const int l8 = lid & 7;
    const int quad = lid >> 3;
    const uint32_t a_lane_off =
        (uint32_t)((m0 + l8 + (quad & 1) * 8) * ROWB + ((quad >> 1) * 8) * 2);
    const uint32_t b_lane_off =
        (uint32_t)((n0 + l8 + (quad >> 1) * 8) * ROWB + ((quad & 1) * 8) * 2);
    const uint32_t whi = sbase + S1_WH + b_lane_off;
    const uint32_t wlo = sbase + S1_WL + b_lane_off;
    const uint32_t ahb = sbase + S1_A + a_lane_off;
    const int tq = lid >> 2;
    const int t4 = lid & 3;

    for (int tile = blockIdx.x; tile < ntiles; tile += gridDim.x) {
        const int row0 = tile * 64;

        __syncthreads();

#pragma unroll
        for (int j = 0; j < 8; j++) {
            int idx = tid + 256 * j;
            int row_l = idx >> 5;
            int c4 = idx & 31;
            float4 v = av[j];
            v.x *= m8[j]; v.y *= m8[j]; v.z *= m8[j]; v.w *= m8[j];
            uint2 hh;
            hh.x = pack2_hi_f16(v.x, v.y);
            hh.y = pack2_hi_f16(v.z, v.w);
            *reinterpret_cast<uint2*>(smem + S1_A + (uint32_t)(row_l * ROWB + c4 * 8)) = hh;
        }
        __syncthreads();

        {
            const int tn = tile + gridDim.x;
            if (tn < ntiles) {
                const long long base = (long long)tn * 2048;
#pragma unroll
                for (int j = 0; j < 8; j++) {
                    long long gi = base + (tid + 256 * j);
                    av[j] = __ldg(A4 + (gi <= max4 ? gi : max4));
                    int row = (int)(gi >> 5);
                    m8[j] = (row < N && __ldg(&mask[row < N ? row : 0]) != 0) ? 1.f : 0.f;
                }
            }
        }

        float acc[2][4][4];
#pragma unroll
        for (int mt = 0; mt < 2; mt++)
#pragma unroll
            for (int nt = 0; nt < 4; nt++) {
                acc[mt][nt][0] = acc[mt][nt][1] = acc[mt][nt][2] = acc[mt][nt][3] = 0.f;
            }

        {
            uint32_t fa[8], fbh[8], fbl[8];
#pragma unroll
            for (int ks = 0; ks < 8; ks++) {
                const uint32_t kb = (uint32_t)(ks * 32);
                LDSM_X4(fa[0], fa[1], fa[2], fa[3], ahb + kb);
                LDSM_X4(fa[4], fa[5], fa[6], fa[7], ahb + 16 * ROWB + kb);
                LDSM_X4(fbh[0], fbh[1], fbh[2], fbh[3], whi + kb);
                LDSM_X4(fbh[4], fbh[5], fbh[6], fbh[7], whi + 16 * ROWB + kb);
                LDSM_X4(fbl[0], fbl[1], fbl[2], fbl[3], wlo + kb);
                LDSM_X4(fbl[4], fbl[5], fbl[6], fbl[7], wlo + 16 * ROWB + kb);
#pragma unroll
                for (int nt = 0; nt < 4; nt++) {
                    MMA16816(acc[0][nt], fa[0], fa[1], fa[2], fa[3], fbh[2 * nt], fbh[2 * nt + 1]);
                    MMA16816(acc[1][nt], fa[4], fa[5], fa[6], fa[7], fbh[2 * nt], fbh[2 * nt + 1]);
                }
#pragma unroll
                for (int nt = 0; nt < 4; nt++) {
                    MMA16816(acc[0][nt], fa[0], fa[1], fa[2], fa[3], fbl[2 * nt], fbl[2 * nt + 1]);
                    MMA16816(acc[1][nt], fa[4], fa[5], fa[6], fa[7], fbl[2 * nt], fbl[2 * nt + 1]);
                }
            }
        }

        float4 ag[8];
#pragma unroll
        for (int j = 0; j < 8; j++) {
            long long gi = (long long)tile * 2048 + (tid + 256 * j);
            ag[j] = __ldg(agg4 + (gi <= max4 ? gi : max4));
        }

        __syncthreads();
#pragma unroll
        for (int mt = 0; mt < 2; mt++) {
            const int rA = m0 + mt * 16 + tq;
#pragma unroll
            for (int nt = 0; nt < 4; nt++) {
                const int c = n0 + nt * 8 + 2 * t4;
                *reinterpret_cast<float2*>(&epi[rA * ROWF + c]) =
                    make_float2(acc[mt][nt][0], acc[mt][nt][1]);
                *reinterpret_cast<float2*>(&epi[(rA + 8) * ROWF + c]) =
                    make_float2(acc[mt][nt][2], acc[mt][nt][3]);
            }
        }
        __syncthreads();

#pragma unroll
        for (int j = 0; j < 8; j++) {
            int idx = tid + 256 * j;
            int row_l = idx >> 5;
            int c4 = idx & 31;
            int rg = row0 + row_l;
            if (rg >= N) continue;
            float4 v = *reinterpret_cast<const float4*>(&epi[row_l * ROWF + c4 * 4]);
            size_t g4 = (size_t)rg * 32 + c4;
            float mm = (__ldg(&mask[rg]) != 0) ? 1.f : 0.f;
            float4 o;
            o.x = tanh_fast(v.x + ag[j].x + mm * bi_r.x + ba_r.x);
            o.y = tanh_fast(v.y + ag[j].y + mm * bi_r.y + ba_r.y);
            o.z = tanh_fast(v.z + ag[j].z + mm * bi_r.z + ba_r.z);
            o.w = tanh_fast(v.w + ag[j].w + mm * bi_r.w + ba_r.w);
            reinterpret_cast<float4*>(outp)[g4] = o;
        }
    }
}

// ---------------------------------------------------------------------------
// Launch
// ---------------------------------------------------------------------------
extern "C" void kernel_launch(void* const* d_in, const int* in_sizes, int n_in,
                              void* d_out, int out_size) {
    const float* x     = (const float*)d_in[0];
    const float* h     = (const float*)d_in[1];
    const float* Win   = (const float*)d_in[2];
    const float* bin   = (const float*)d_in[3];
    const float* Waggr = (const float*)d_in[4];
    const float* baggr = (const float*)d_in[5];
    const int* mask    = (const int*)d_in[6];
    const int* esrc    = (const int*)d_in[7];
    const int* edst    = (const int*)d_in[8];
    float* out = (float*)d_out;

    const int N = in_sizes[0] / 128;
    const int E = in_sizes[7];
    const int ntiles = (N + 63) / 64;

    static int smem_set = 0;
    if (!smem_set) {
        cudaFuncSetAttribute(gemm0_kernel, cudaFuncAttributeMaxDynamicSharedMemorySize,
                             (int)S0_TOTAL);
        cudaFuncSetAttribute(gemm1_kernel, cudaFuncAttributeMaxDynamicSharedMemorySize,
                             (int)S1_TOTAL);
        smem_set = 1;
    }

    unsigned int* wimg_dev = nullptr;
    cudaGetSymbolAddress((void**)&wimg_dev, g_wimg);

    prep_w<<<128, 64>>>(Win, Waggr);
    // gemm0: g_hw = f16(h @ Wag_hi); zero g_agg. 3 CTAs/SM persistent.
    gemm0_kernel<<<444, 256, S0_TOTAL>>>(h, wimg_dev + 2 * 8192, N, ntiles);
    // scatter: g_agg[dst] += f32(g_hw[src])
    const int warps_needed = (E + 3) / 4;
    scatter_kernel<<<(warps_needed + 7) / 8, 256>>>(esrc, edst, E);
    // gemm1: out = tanh(x_m @ W_in + g_agg + m*b_in + b_aggr)
    gemm1_kernel<<<296, 256, S1_TOTAL>>>(x, wimg_dev, bin, baggr, mask, out, N,
                                         ntiles);
}